// round 3
// baseline (speedup 1.0000x reference)
#include <cuda_runtime.h>
#include <math.h>

#define BATCH 8192
#define CIN   256
#define NK    4
#define COUT  64
#define OCT   (NK * COUT)
#define BT 32
#define OT 64
#define CC 8
#define KBT 32

__device__ float g_Y[(size_t)BATCH * OCT * 4];
__device__ float g_pooled[(size_t)BATCH * CIN];
__device__ float g_attn[(size_t)BATCH * NK];

#define FMA_F32X2(d, a, b, c) \
    asm("fma.rn.f32x2 %0, %1, %2, %3;" : "=l"(d) : "l"(a), "l"(b), "l"(c))

__device__ __forceinline__ unsigned long long pack2(float lo, float hi) {
    unsigned long long r;
    asm("mov.b64 %0, {%1, %2};" : "=l"(r) : "r"(__float_as_uint(lo)), "r"(__float_as_uint(hi)));
    return r;
}
__device__ __forceinline__ void unpack2(unsigned long long v, float& lo, float& hi) {
    unsigned int a, b;
    asm("mov.b64 {%0, %1}, %2;" : "=r"(a), "=r"(b) : "l"(v));
    lo = __uint_as_float(a);
    hi = __uint_as_float(b);
}

// ---------------------------------------------------------------------------
// Kernel 1: conv GEMM  Y[b,o',p] = sum_{c,ij} x[b,c,patch(p,ij)] * W[o',c,ij]
// packed over sample pairs via fma.rn.f32x2; fused GAP on blockIdx.y==0.
// ---------------------------------------------------------------------------
__global__ __launch_bounds__(256, 2) void conv_kernel(
    const float* __restrict__ x, const float* __restrict__ w)
{
    __shared__ __align__(16) float Xs[CC * 16 * BT];   // [c][q][s]
    __shared__ __align__(16) float Ws[CC * OT * 12];   // [c][o][ij pad 12]

    const int tid = threadIdx.x;
    const int b0  = blockIdx.x * BT;
    const int o0  = blockIdx.y * OT;
    const int s0  = (tid >> 4) * 2;
    const int to  = (tid & 15) * 4;

    unsigned long long acc2[4][4];
#pragma unroll
    for (int a = 0; a < 4; a++)
#pragma unroll
        for (int p = 0; p < 4; p++) acc2[a][p] = 0ull;

    for (int cc = 0; cc < CIN; cc += CC) {
#pragma unroll
        for (int r = 0; r < 4; r++) {
            int l4  = tid + r * 256;
            int c   = l4 >> 7;
            int rem = l4 & 127;
            int s   = rem >> 2;
            int q4  = rem & 3;
            float4 v = reinterpret_cast<const float4*>(x)[((size_t)(b0 + s) * CIN + cc + c) * 4 + q4];
            Xs[(c * 16 + q4 * 4 + 0) * BT + s] = v.x;
            Xs[(c * 16 + q4 * 4 + 1) * BT + s] = v.y;
            Xs[(c * 16 + q4 * 4 + 2) * BT + s] = v.z;
            Xs[(c * 16 + q4 * 4 + 3) * BT + s] = v.w;
        }
#pragma unroll
        for (int r = 0; r < 18; r++) {
            int l  = tid + r * 256;
            int c  = l / 576;
            int rm = l - c * 576;
            int o  = rm / 9;
            int ij = rm - o * 9;
            Ws[(c * OT + o) * 12 + ij] = w[((size_t)(o0 + o) * CIN + cc + c) * 9 + ij];
        }
        __syncthreads();

        if (blockIdx.y == 0) {
            int s = tid >> 3, c = tid & 7;
            float sum = 0.f;
#pragma unroll
            for (int q = 0; q < 16; q++) sum += Xs[(c * 16 + q) * BT + s];
            g_pooled[(size_t)(b0 + s) * CIN + cc + c] = sum * (1.f / 16.f);
        }

#pragma unroll
        for (int c = 0; c < CC; c++) {
            unsigned long long xv2[16];
#pragma unroll
            for (int q = 0; q < 16; q++)
                xv2[q] = *reinterpret_cast<const unsigned long long*>(&Xs[(c * 16 + q) * BT + s0]);
#pragma unroll
            for (int oi = 0; oi < 4; oi++) {
                float wvf[12];
#pragma unroll
                for (int q4 = 0; q4 < 3; q4++)
                    *reinterpret_cast<float4*>(&wvf[q4 * 4]) =
                        reinterpret_cast<float4*>(Ws)[(c * OT + to + oi) * 3 + q4];
                unsigned long long wp[9];
#pragma unroll
                for (int k = 0; k < 9; k++) wp[k] = pack2(wvf[k], wvf[k]);
#pragma unroll
                for (int p = 0; p < 4; p++) {
                    const int ph = p >> 1, pw = p & 1;
#pragma unroll
                    for (int i = 0; i < 3; i++)
#pragma unroll
                        for (int j = 0; j < 3; j++)
                            FMA_F32X2(acc2[oi][p], xv2[(ph + i) * 4 + pw + j],
                                      wp[i * 3 + j], acc2[oi][p]);
                }
            }
        }
        __syncthreads();
    }

#pragma unroll
    for (int oi = 0; oi < 4; oi++) {
        float lo[4], hi[4];
#pragma unroll
        for (int p = 0; p < 4; p++) unpack2(acc2[oi][p], lo[p], hi[p]);
        reinterpret_cast<float4*>(g_Y)[(size_t)(b0 + s0) * OCT + o0 + to + oi] =
            make_float4(lo[0], lo[1], lo[2], lo[3]);
        reinterpret_cast<float4*>(g_Y)[(size_t)(b0 + s0 + 1) * OCT + o0 + to + oi] =
            make_float4(hi[0], hi[1], hi[2], hi[3]);
    }
}

// ---------------------------------------------------------------------------
// Kernel 2: attention  pooled -> fc1 -> relu -> fc2 -> softmax(/34)
// ---------------------------------------------------------------------------
__global__ __launch_bounds__(256) void attn_kernel(
    const float* __restrict__ fc1w, const float* __restrict__ fc1b,
    const float* __restrict__ fc2w, const float* __restrict__ fc2b)
{
    __shared__ float ps[256];
    __shared__ float hpart[4][64];
    __shared__ float hid[64];
    __shared__ float logit[4];
    __shared__ float w2[256];
    __shared__ float b1[64];
    __shared__ float b2[4];

    const int tid = threadIdx.x;
    w2[tid] = fc2w[tid & 255];
    if (tid < 64) b1[tid] = fc1b[tid];
    if (tid < 4)  b2[tid] = fc2b[tid];

    const int h = tid >> 2;
    const int part = tid & 3;

    for (int s = 0; s < 16; s++) {
        const int b = blockIdx.x * 16 + s;
        __syncthreads();
        ps[tid] = g_pooled[(size_t)b * 256 + tid];
        __syncthreads();
        {
            const float4* wr = reinterpret_cast<const float4*>(fc1w + (size_t)h * 256 + part * 64);
            const float4* pr = reinterpret_cast<const float4*>(ps + part * 64);
            float sum = 0.f;
#pragma unroll
            for (int q = 0; q < 16; q++) {
                float4 a = wr[q]; float4 bb = pr[q];
                sum = fmaf(a.x, bb.x, sum); sum = fmaf(a.y, bb.y, sum);
                sum = fmaf(a.z, bb.z, sum); sum = fmaf(a.w, bb.w, sum);
            }
            hpart[part][h] = sum;
        }
        __syncthreads();
        if (tid < 64)
            hid[tid] = fmaxf(hpart[0][tid] + hpart[1][tid] + hpart[2][tid] + hpart[3][tid] + b1[tid], 0.f);
        __syncthreads();
        if (tid < 4) {
            float sm = 0.f;
#pragma unroll
            for (int k2 = 0; k2 < 64; k2++) sm = fmaf(hid[k2], w2[tid * 64 + k2], sm);
            logit[tid] = (sm + b2[tid]) * (1.0f / 34.0f);
        }
        __syncthreads();
        if (tid == 0) {
            float m  = fmaxf(fmaxf(logit[0], logit[1]), fmaxf(logit[2], logit[3]));
            float e0 = expf(logit[0] - m), e1 = expf(logit[1] - m);
            float e2 = expf(logit[2] - m), e3 = expf(logit[3] - m);
            float inv = 1.f / (e0 + e1 + e2 + e3);
            g_attn[(size_t)b * 4 + 0] = e0 * inv;
            g_attn[(size_t)b * 4 + 1] = e1 * inv;
            g_attn[(size_t)b * 4 + 2] = e2 * inv;
            g_attn[(size_t)b * 4 + 3] = e3 * inv;
        }
    }
}

// ---------------------------------------------------------------------------
// B-spline bases, grid matches the reference knots bit-exactly.
// ---------------------------------------------------------------------------
__device__ __forceinline__ void bspline8(float t, float* __restrict__ o8)
{
    float g[12];
#pragma unroll
    for (int j = 0; j < 12; j++)
        g[j] = __fadd_rn(__fmul_rn((float)(j - 3), 0.4f), -1.0f);
    float b[11];
#pragma unroll
    for (int j = 0; j < 11; j++)
        b[j] = (t >= g[j] && t < g[j + 1]) ? 1.0f : 0.0f;
#pragma unroll
    for (int k = 1; k <= 3; k++) {
#pragma unroll
        for (int j = 0; j < 10; j++) {
            if (j < 11 - k) {
                float left  = (t - g[j])         * (1.0f / (g[j + k] - g[j]));
                float right = (g[j + k + 1] - t) * (1.0f / (g[j + k + 1] - g[j + 1]));
                b[j] = left * b[j] + right * b[j + 1];
            }
        }
    }
#pragma unroll
    for (int j = 0; j < 8; j++) o8[j] = b[j];
}

// ---------------------------------------------------------------------------
// Kernel 3: attn-combine + KANLinear
// ---------------------------------------------------------------------------
#define KAN_SMEM_FLOATS (KBT*256 + KBT*256 + 32*8*64 + 32*64 + KBT*32*8)
#define KAN_SMEM_BYTES  (KAN_SMEM_FLOATS * 4)

__global__ __launch_bounds__(256) void kan_kernel(
    const float* __restrict__ bias,
    const float* __restrict__ base_w,
    const float* __restrict__ spline_w,
    const float* __restrict__ scaler,
    float* __restrict__ out)
{
    extern __shared__ __align__(16) float sm[];
    float* feat = sm;                   // [32][256]
    float* sil  = feat + KBT * 256;     // [32][256]
    float* wsp  = sil  + KBT * 256;     // [i(32)][g(8)][o(64)]
    float* wb   = wsp  + 32 * 8 * 64;   // [i(32)][o(64)]
    float* bas  = wb   + 32 * 64;       // [s(32)][i(32)][g(8)]
    __shared__ float attn_s[KBT * 4];
    __shared__ float biass[NK * COUT];

    const int tid = threadIdx.x;
    const int b0  = blockIdx.x * KBT;

    if (tid < 128) attn_s[tid] = g_attn[(size_t)b0 * 4 + tid];
    biass[tid] = bias[tid & 255];
    __syncthreads();

    {   // feat + silu(feat)
        const int s = tid >> 3, lane = tid & 7;
        const size_t yb = (size_t)(b0 + s) * (OCT * 4);
        const float a0 = attn_s[s * 4 + 0], a1 = attn_s[s * 4 + 1];
        const float a2 = attn_s[s * 4 + 2], a3 = attn_s[s * 4 + 3];
#pragma unroll 4
        for (int m = 0; m < 32; m++) {
            int i = m * 8 + lane;
            float f = a0 * g_Y[yb + i] + a1 * g_Y[yb + 256 + i]
                    + a2 * g_Y[yb + 512 + i] + a3 * g_Y[yb + 768 + i];
            int o = i >> 2;
            f += a0 * biass[o] + a1 * biass[64 + o] + a2 * biass[128 + o] + a3 * biass[192 + o];
            feat[s * 256 + i] = f;
            sil[s * 256 + i]  = f / (1.f + expf(-f));
        }
    }

    const int og = tid & 15;
    const int sg = tid >> 4;
    float acc[2][4] = {{0.f, 0.f, 0.f, 0.f}, {0.f, 0.f, 0.f, 0.f}};

    for (int ic = 0; ic < 8; ic++) {
        const int i0 = ic * 32;
        __syncthreads();

#pragma unroll
        for (int r = 0; r < 16; r++) {
            int l4 = tid + r * 256;
            int o  = l4 & 63;
            int ig = l4 >> 6;
            int i  = ig >> 1;
            int gh = ig & 1;
            float4 v = reinterpret_cast<const float4*>(spline_w)[((size_t)o * 256 + i0 + i) * 2 + gh];
            float sc = scaler[(size_t)o * 256 + i0 + i];
            int gb = gh * 4;
            wsp[(i * 8 + gb + 0) * 64 + o] = v.x * sc;
            wsp[(i * 8 + gb + 1) * 64 + o] = v.y * sc;
            wsp[(i * 8 + gb + 2) * 64 + o] = v.z * sc;
            wsp[(i * 8 + gb + 3) * 64 + o] = v.w * sc;
        }
#pragma unroll
        for (int r = 0; r < 8; r++) {
            int l = tid + r * 256;
            int o = l & 63;
            int i = l >> 6;
            wb[i * 64 + o] = base_w[(size_t)o * 256 + i0 + i];
        }
#pragma unroll
        for (int r = 0; r < 4; r++) {
            int task = tid + r * 256;
            int s = task >> 5;
            int i = task & 31;
            float bb8[8];
            bspline8(feat[s * 256 + i0 + i], bb8);
            float4* dst = reinterpret_cast<float4*>(&bas[(s * 32 + i) * 8]);
            dst[0] = make_float4(bb8[0], bb8[1], bb8[2], bb8[3]);
            dst[1] = make_float4(bb8[4], bb8[5], bb8[6], bb8[7]);
        }
        __syncthreads();

        for (int i = 0; i < 32; i++) {
            float4 wbv = *reinterpret_cast<const float4*>(&wb[i * 64 + og * 4]);
            float wvp[32];
#pragma unroll
            for (int g = 0; g < 8; g++)
                *reinterpret_cast<float4*>(&wvp[g * 4]) =
                    *reinterpret_cast<const float4*>(&wsp[(i * 8 + g) * 64 + og * 4]);
#pragma unroll
            for (int ss = 0; ss < 2; ss++) {
                const int s = sg * 2 + ss;
                const float sv = sil[s * 256 + i0 + i];
                const float4* bp = reinterpret_cast<const float4*>(&bas[(s * 32 + i) * 8]);
                float4 bA = bp[0], bB = bp[1];
                float bv[8] = {bA.x, bA.y, bA.z, bA.w, bB.x, bB.y, bB.z, bB.w};
                acc[ss][0] = fmaf(sv, wbv.x, acc[ss][0]);
                acc[ss][1] = fmaf(sv, wbv.y, acc[ss][1]);
                acc[ss][2] = fmaf(sv, wbv.z, acc[ss][2]);
                acc[ss][3] = fmaf(sv, wbv.w, acc[ss][3]);
#pragma unroll
                for (int g = 0; g < 8; g++) {
                    acc[ss][0] = fmaf(bv[g], wvp[g * 4 + 0], acc[ss][0]);
                    acc[ss][1] = fmaf(bv[g], wvp[g * 4 + 1], acc[ss][1]);
                    acc[ss][2] = fmaf(bv[g], wvp[g * 4 + 2], acc[ss][2]);
                    acc[ss][3] = fmaf(bv[g], wvp[g * 4 + 3], acc[ss][3]);
                }
            }
        }
    }

#pragma unroll
    for (int ss = 0; ss < 2; ss++) {
        const int b = b0 + sg * 2 + ss;
        *reinterpret_cast<float4*>(&out[(size_t)b * 64 + og * 4]) =
            make_float4(acc[ss][0], acc[ss][1], acc[ss][2], acc[ss][3]);
    }
}

extern "C" void kernel_launch(void* const* d_in, const int* in_sizes, int n_in,
                              void* d_out, int out_size)
{
    const float* x    = (const float*)d_in[0];
    const float* w    = (const float*)d_in[1];
    const float* bias = (const float*)d_in[2];
    const float* fc1w = (const float*)d_in[3];
    const float* fc1b = (const float*)d_in[4];
    const float* fc2w = (const float*)d_in[5];
    const float* fc2b = (const float*)d_in[6];
    const float* kbw  = (const float*)d_in[7];
    const float* ksw  = (const float*)d_in[8];
    const float* kss  = (const float*)d_in[9];
    float* out = (float*)d_out;

    cudaFuncSetAttribute(kan_kernel, cudaFuncAttributeMaxDynamicSharedMemorySize, KAN_SMEM_BYTES);

    conv_kernel<<<dim3(BATCH / BT, OCT / OT), 256>>>(x, w);
    attn_kernel<<<BATCH / 16, 256>>>(fc1w, fc1b, fc2w, fc2b);
    kan_kernel<<<BATCH / KBT, 256, KAN_SMEM_BYTES>>>(bias, kbw, ksw, kss, out);
}

// round 6
// speedup vs baseline: 1.7698x; 1.7698x over previous
#include <cuda_runtime.h>
#include <cuda_bf16.h>
#include <math.h>
#include <stdint.h>

#define BATCH 8192
#define CIN   256
#define NK    4
#define COUT  64
#define KDIM  4096            // CIN*16 zero-padded K
#define NDIM  1024            // 64 o * 16 idx, idx = (nk>>1)*8 + p*2 + (nk&1)
#define KBT   32

// GEMM tiling
#define MT 128
#define NT 256
#define KC 64                 // bf16 per K-chunk = 128 bytes
#define NCHUNK (KDIM / KC)    // 64

// ---------------------------------------------------------------------------
// Static device scratch
// ---------------------------------------------------------------------------
__device__ __nv_bfloat16 g_Xh[(size_t)BATCH * KDIM];
__device__ __nv_bfloat16 g_Xl[(size_t)BATCH * KDIM];
__device__ __nv_bfloat16 g_Wh[(size_t)NDIM * KDIM];
__device__ __nv_bfloat16 g_Wl[(size_t)NDIM * KDIM];
__device__ float g_feat[(size_t)BATCH * 256];
__device__ float g_pooled[(size_t)BATCH * CIN];
__device__ float g_attn[(size_t)BATCH * NK];

// ---------------------------------------------------------------------------
// PTX helpers (base ISA only: cp.async, ldmatrix, mma.sync)
// ---------------------------------------------------------------------------
__device__ __forceinline__ unsigned smem_u32(const void* p) {
    unsigned a;
    asm("{ .reg .u64 t; cvta.to.shared.u64 t, %1; cvt.u32.u64 %0, t; }" : "=r"(a) : "l"(p));
    return a;
}
__device__ __forceinline__ void cp_async16(unsigned saddr, const void* g) {
    asm volatile("cp.async.cg.shared.global [%0], [%1], 16;" :: "r"(saddr), "l"(g));
}
#define CP_COMMIT() asm volatile("cp.async.commit_group;" ::: "memory")
#define CP_WAIT1()  asm volatile("cp.async.wait_group 1;" ::: "memory")

#define LDSM_X4(r0, r1, r2, r3, addr) \
    asm volatile("ldmatrix.sync.aligned.m8n8.x4.shared.b16 {%0,%1,%2,%3}, [%4];" \
                 : "=r"(r0), "=r"(r1), "=r"(r2), "=r"(r3) : "r"(addr))

#define MMA16816(c, a, b0, b1) \
    asm volatile("mma.sync.aligned.m16n8k16.row.col.f32.bf16.bf16.f32 " \
                 "{%0,%1,%2,%3}, {%4,%5,%6,%7}, {%8,%9}, {%0,%1,%2,%3};" \
                 : "+f"((c)[0]), "+f"((c)[1]), "+f"((c)[2]), "+f"((c)[3]) \
                 : "r"((a)[0]), "r"((a)[1]), "r"((a)[2]), "r"((a)[3]), \
                   "r"(b0), "r"(b1))

#define SWZ(o) ((o) ^ (((o) >> 3) & 0x70))

// ---------------------------------------------------------------------------
// Prep 1: x fp32 -> Xh/Xl bf16 (row-major [B][4096]) + fused GAP
// ---------------------------------------------------------------------------
__global__ __launch_bounds__(256) void prep_x_kernel(const float* __restrict__ x)
{
    const int b = blockIdx.x, c = threadIdx.x;
    const size_t base = ((size_t)b * CIN + c) * 16;
    const float4* src = reinterpret_cast<const float4*>(x + base);
    float4 v[4];
#pragma unroll
    for (int i = 0; i < 4; i++) v[i] = src[i];
    const float* f = reinterpret_cast<const float*>(v);

    __nv_bfloat16 h[16], l[16];
    float sum = 0.f;
#pragma unroll
    for (int e = 0; e < 16; e++) {
        float fv = f[e];
        sum += fv;
        h[e] = __float2bfloat16(fv);
        l[e] = __float2bfloat16(fv - __bfloat162float(h[e]));
    }
    g_pooled[(size_t)b * CIN + c] = sum * (1.f / 16.f);

    uint4* dh = reinterpret_cast<uint4*>(g_Xh + base);
    uint4* dl = reinterpret_cast<uint4*>(g_Xl + base);
    dh[0] = reinterpret_cast<const uint4*>(h)[0];
    dh[1] = reinterpret_cast<const uint4*>(h)[1];
    dl[0] = reinterpret_cast<const uint4*>(l)[0];
    dl[1] = reinterpret_cast<const uint4*>(l)[1];
}

// ---------------------------------------------------------------------------
// Prep 2: weights -> W'' [n][k] bf16 hi/lo.
// n = o*16 + idx, idx = b3*8 + p*2 + b0, nk = 2*b3 + b0 (epilogue-friendly).
// k = c*16 + q; zero where the 3x3 window (shifted by position p) misses q.
// ---------------------------------------------------------------------------
__global__ __launch_bounds__(256) void prep_w_kernel(const float* __restrict__ w)
{
    const int n = blockIdx.x, c = threadIdx.x;
    const int o = n >> 4, idx = n & 15;
    const int b3 = idx >> 3, p = (idx >> 1) & 3, b0 = idx & 1;
    const int nk = 2 * b3 + b0;
    const int ph = p >> 1, pw = p & 1;
    const float* wr = w + ((size_t)(nk * COUT + o) * CIN + c) * 9;

    __nv_bfloat16 h[16], l[16];
#pragma unroll
    for (int q = 0; q < 16; q++) {
        int i = (q >> 2) - ph, j = (q & 3) - pw;
        float val = (i >= 0 && i < 3 && j >= 0 && j < 3) ? wr[i * 3 + j] : 0.f;
        h[q] = __float2bfloat16(val);
        l[q] = __float2bfloat16(val - __bfloat162float(h[q]));
    }
    const size_t base = (size_t)n * KDIM + (size_t)c * 16;
    uint4* dh = reinterpret_cast<uint4*>(g_Wh + base);
    uint4* dl = reinterpret_cast<uint4*>(g_Wl + base);
    dh[0] = reinterpret_cast<const uint4*>(h)[0];
    dh[1] = reinterpret_cast<const uint4*>(h)[1];
    dl[0] = reinterpret_cast<const uint4*>(l)[0];
    dl[1] = reinterpret_cast<const uint4*>(l)[1];
}

// ---------------------------------------------------------------------------
// Attention: pooled -> fc1 -> relu -> fc2 -> softmax(/34)
// ---------------------------------------------------------------------------
__global__ __launch_bounds__(256) void attn_kernel(
    const float* __restrict__ fc1w, const float* __restrict__ fc1b,
    const float* __restrict__ fc2w, const float* __restrict__ fc2b)
{
    __shared__ float ps[256];
    __shared__ float hpart[4][64];
    __shared__ float hid[64];
    __shared__ float logit[4];
    __shared__ float w2[256];
    __shared__ float b1[64];
    __shared__ float b2[4];

    const int tid = threadIdx.x;
    w2[tid] = fc2w[tid & 255];
    if (tid < 64) b1[tid] = fc1b[tid];
    if (tid < 4)  b2[tid] = fc2b[tid];

    const int h = tid >> 2;
    const int part = tid & 3;

    for (int s = 0; s < 16; s++) {
        const int b = blockIdx.x * 16 + s;
        __syncthreads();
        ps[tid] = g_pooled[(size_t)b * 256 + tid];
        __syncthreads();
        {
            const float4* wr = reinterpret_cast<const float4*>(fc1w + (size_t)h * 256 + part * 64);
            const float4* pr = reinterpret_cast<const float4*>(ps + part * 64);
            float sum = 0.f;
#pragma unroll
            for (int q = 0; q < 16; q++) {
                float4 a = wr[q]; float4 bb = pr[q];
                sum = fmaf(a.x, bb.x, sum); sum = fmaf(a.y, bb.y, sum);
                sum = fmaf(a.z, bb.z, sum); sum = fmaf(a.w, bb.w, sum);
            }
            hpart[part][h] = sum;
        }
        __syncthreads();
        if (tid < 64)
            hid[tid] = fmaxf(hpart[0][tid] + hpart[1][tid] + hpart[2][tid] + hpart[3][tid] + b1[tid], 0.f);
        __syncthreads();
        if (tid < 4) {
            float sm = 0.f;
#pragma unroll
            for (int k2 = 0; k2 < 64; k2++) sm = fmaf(hid[k2], w2[tid * 64 + k2], sm);
            logit[tid] = (sm + b2[tid]) * (1.0f / 34.0f);
        }
        __syncthreads();
        if (tid == 0) {
            float m  = fmaxf(fmaxf(logit[0], logit[1]), fmaxf(logit[2], logit[3]));
            float e0 = expf(logit[0] - m), e1 = expf(logit[1] - m);
            float e2 = expf(logit[2] - m), e3 = expf(logit[3] - m);
            float inv = 1.f / (e0 + e1 + e2 + e3);
            g_attn[(size_t)b * 4 + 0] = e0 * inv;
            g_attn[(size_t)b * 4 + 1] = e1 * inv;
            g_attn[(size_t)b * 4 + 2] = e2 * inv;
            g_attn[(size_t)b * 4 + 3] = e3 * inv;
        }
    }
}

// ---------------------------------------------------------------------------
// GEMM via ldmatrix + mma.sync (bf16 hi/lo, 3 passes, fp32 reg accum).
// CTA 128x256, 8 warps (2m x 4n), warp tile 64x64, K-chunk 64, 2-stage cp.async.
// Epilogue fuses attn-combine + bias -> g_feat.
// smem stage layout: Ah[16K] Al[16K] Bh[32K] Bl[32K] = 96KB; 2 stages = 192KB.
// ---------------------------------------------------------------------------
#define ST_AH 0
#define ST_AL (MT * 128)
#define ST_BH (2 * MT * 128)
#define ST_BL (2 * MT * 128 + NT * 128)
#define ST_SZ (2 * MT * 128 + 2 * NT * 128)   // 98304
#define GEMM_SMEM (2 * ST_SZ)                 // 196608

__global__ __launch_bounds__(256, 1) void gemm_kernel(const float* __restrict__ bias)
{
    extern __shared__ __align__(1024) char smem[];
    __shared__ float bias_s[256];

    const unsigned sb = smem_u32(smem);
    const int tid = threadIdx.x;
    const int wid = tid >> 5, lane = tid & 31;
    const int wm = wid >> 2, wn = wid & 3;
    const int m0 = blockIdx.x * MT;
    const int n0 = blockIdx.y * NT;

    bias_s[tid] = bias[tid];

    const char* Xh = (const char*)g_Xh;
    const char* Xl = (const char*)g_Xl;
    const char* Wh = (const char*)g_Wh;
    const char* Wl = (const char*)g_Wl;

    // ---- chunk loader: 24 cp.async16 per thread ----
    auto load_chunk = [&](int ch, int stg) {
        const unsigned st = sb + stg * ST_SZ;
        const size_t kb = (size_t)ch * 128;   // byte offset within a row
#pragma unroll
        for (int i = 0; i < 4; i++) {
            int s = tid + i * 256;
            int row = s >> 3, seg = s & 7;
            unsigned so = SWZ(row * 128 + seg * 16);
            size_t g = (size_t)(m0 + row) * (KDIM * 2) + kb + seg * 16;
            cp_async16(st + ST_AH + so, Xh + g);
            cp_async16(st + ST_AL + so, Xl + g);
        }
#pragma unroll
        for (int i = 0; i < 8; i++) {
            int s = tid + i * 256;
            int row = s >> 3, seg = s & 7;
            unsigned so = SWZ(row * 128 + seg * 16);
            size_t g = (size_t)(n0 + row) * (KDIM * 2) + kb + seg * 16;
            cp_async16(st + ST_BH + so, Wh + g);
            cp_async16(st + ST_BL + so, Wl + g);
        }
    };

    float cAcc[4][8][4];
#pragma unroll
    for (int m = 0; m < 4; m++)
#pragma unroll
        for (int n = 0; n < 8; n++)
#pragma unroll
            for (int r = 0; r < 4; r++) cAcc[m][n][r] = 0.f;

    load_chunk(0, 0); CP_COMMIT();
    load_chunk(1, 1); CP_COMMIT();

    const int arow = (lane & 15);
    const int aseg = (lane >> 4) << 4;

    for (int ch = 0; ch < NCHUNK; ch++) {
        const int stg = ch & 1;
        const unsigned st = sb + stg * ST_SZ;
        CP_WAIT1();
        __syncthreads();

#pragma unroll
        for (int ks = 0; ks < 4; ks++) {
            const int kb = ks * 32 + aseg;
            unsigned ah[4][4], al[4][4], bh[4][4], bl[4][4];
#pragma unroll
            for (int mt = 0; mt < 4; mt++) {
                int r = wm * 64 + mt * 16 + arow;
                unsigned so = SWZ(r * 128 + kb);
                LDSM_X4(ah[mt][0], ah[mt][1], ah[mt][2], ah[mt][3], st + ST_AH + so);
                LDSM_X4(al[mt][0], al[mt][1], al[mt][2], al[mt][3], st + ST_AL + so);
            }
#pragma unroll
            for (int nt2 = 0; nt2 < 4; nt2++) {
                int r = wn * 64 + nt2 * 16 + arow;
                unsigned so = SWZ(r * 128 + kb);
                LDSM_X4(bh[nt2][0], bh[nt2][1], bh[nt2][2], bh[nt2][3], st + ST_BH + so);
                LDSM_X4(bl[nt2][0], bl[nt2][1], bl[nt2][2], bl[nt2][3], st + ST_BL + so);
            }
            // B n8-frag j (=2*nt2+b3): {reg b3, reg b3+2}
#pragma unroll
            for (int mt = 0; mt < 4; mt++)
#pragma unroll
                for (int nt2 = 0; nt2 < 4; nt2++)
#pragma unroll
                    for (int b3 = 0; b3 < 2; b3++) {
                        float* c = cAcc[mt][nt2 * 2 + b3];
                        MMA16816(c, ah[mt], bh[nt2][b3], bh[nt2][b3 + 2]);   // hh
                        MMA16816(c, al[mt], bh[nt2][b3], bh[nt2][b3 + 2]);   // lh
                        MMA16816(c, ah[mt], bl[nt2][b3], bl[nt2][b3 + 2]);   // hl
                    }
        }

        __syncthreads();
        if (ch + 2 < NCHUNK) load_chunk(ch + 2, stg);
        CP_COMMIT();
    }

    // ---- epilogue: fused attn combine + bias -> g_feat ----
    const int p = lane & 3;
#pragma unroll
    for (int mt = 0; mt < 4; mt++) {
#pragma unroll
        for (int h = 0; h < 2; h++) {
            const int b = m0 + wm * 64 + mt * 16 + (lane >> 2) + h * 8;
            const float4 av = *reinterpret_cast<const float4*>(g_attn + (size_t)b * 4);
            const float a[4] = {av.x, av.y, av.z, av.w};
#pragma unroll
            for (int t2 = 0; t2 < 4; t2++) {
                const int o = (n0 >> 4) + wn * 4 + t2;
                float r = 0.f;
#pragma unroll
                for (int b3 = 0; b3 < 2; b3++)
#pragma unroll
                    for (int e = 0; e < 2; e++) {
                        const int nk = 2 * b3 + e;
                        r += a[nk] * (cAcc[mt][t2 * 2 + b3][h * 2 + e] + bias_s[nk * 64 + o]);
                    }
                g_feat[(size_t)b * 256 + o * 4 + p] = r;
            }
        }
    }
}

// ---------------------------------------------------------------------------
// B-spline bases, grid matches the reference knots bit-exactly.
// ---------------------------------------------------------------------------
__device__ __forceinline__ void bspline8(float t, float* __restrict__ o8)
{
    float g[12];
#pragma unroll
    for (int j = 0; j < 12; j++)
        g[j] = __fadd_rn(__fmul_rn((float)(j - 3), 0.4f), -1.0f);
    float b[11];
#pragma unroll
    for (int j = 0; j < 11; j++)
        b[j] = (t >= g[j] && t < g[j + 1]) ? 1.0f : 0.0f;
#pragma unroll
    for (int k = 1; k <= 3; k++) {
#pragma unroll
        for (int j = 0; j < 10; j++) {
            if (j < 11 - k) {
                float left  = (t - g[j])         * (1.0f / (g[j + k] - g[j]));
                float right = (g[j + k + 1] - t) * (1.0f / (g[j + k + 1] - g[j + 1]));
                b[j] = left * b[j] + right * b[j + 1];
            }
        }
    }
#pragma unroll
    for (int j = 0; j < 8; j++) o8[j] = b[j];
}

// ---------------------------------------------------------------------------
// KANLinear on g_feat
// ---------------------------------------------------------------------------
#define KAN_SMEM_FLOATS (KBT*256 + KBT*256 + 32*8*64 + 32*64 + KBT*32*8)
#define KAN_SMEM_BYTES  (KAN_SMEM_FLOATS * 4)

__global__ __launch_bounds__(256) void kan_kernel(
    const float* __restrict__ base_w,
    const float* __restrict__ spline_w,
    const float* __restrict__ scaler,
    float* __restrict__ out)
{
    extern __shared__ __align__(16) float sm[];
    float* feat = sm;                   // [32][256]
    float* sil  = feat + KBT * 256;     // [32][256]
    float* wsp  = sil  + KBT * 256;     // [i(32)][g(8)][o(64)]
    float* wb   = wsp  + 32 * 8 * 64;   // [i(32)][o(64)]
    float* bas  = wb   + 32 * 64;       // [s(32)][i(32)][g(8)]

    const int tid = threadIdx.x;
    const int b0  = blockIdx.x * KBT;

    {   // load feat, compute silu
        const int s = tid >> 3, lane = tid & 7;
        const size_t fb = (size_t)(b0 + s) * 256;
#pragma unroll 4
        for (int m = 0; m < 32; m++) {
            int i = m * 8 + lane;
            float f = g_feat[fb + i];
            feat[s * 256 + i] = f;
            sil[s * 256 + i]  = f / (1.f + expf(-f));
        }
    }

    const int og = tid & 15;
    const int sg = tid >> 4;
    float acc[2][4] = {{0.f, 0.f, 0.f, 0.f}, {0.f, 0.f, 0.f, 0.f}};

    for (int ic = 0; ic < 8; ic++) {
        const int i0 = ic * 32;
        __syncthreads();

#pragma unroll
        for (int r = 0; r < 16; r++) {
            int l4 = tid + r * 256;
            int o  = l4 & 63;
            int ig = l4 >> 6;
            int i  = ig >> 1;
            int gh = ig & 1;
            float4 v = reinterpret_cast<const float4*>(spline_w)[((size_t)o * 256 + i0 + i) * 2 + gh];
            float sc = scaler[(size_t)o * 256 + i0 + i];
            int gb = gh * 4;
            wsp[(i * 8 + gb + 0) * 64 + o] = v.x * sc;
            wsp[(i * 8 + gb + 1) * 64 + o] = v.y * sc;
            wsp[(i * 8 + gb + 2) * 64 + o] = v.z * sc;
            wsp[(i * 8 + gb + 3) * 64 + o] = v.w * sc;
        }
#pragma unroll
        for (int r = 0; r < 8; r++) {
            int l = tid + r * 256;
            int o = l & 63;
            int i = l >> 6;
            wb[i * 64 + o] = base_w[(size_t)o * 256 + i0 + i];
        }
#pragma unroll
        for (int r = 0; r < 4; r++) {
            int task = tid + r * 256;
            int s = task >> 5;
            int i = task & 31;
            float bb8[8];
            bspline8(feat[s * 256 + i0 + i], bb8);
            float4* dst = reinterpret_cast<float4*>(&bas[(s * 32 + i) * 8]);
            dst[0] = make_float4(bb8[0], bb8[1], bb8[2], bb8[3]);
            dst[1] = make_float4(bb8[4], bb8[5], bb8[6], bb8[7]);
        }
        __syncthreads();

        for (int i = 0; i < 32; i++) {
            float4 wbv = *reinterpret_cast<const float4*>(&wb[i * 64 + og * 4]);
            float wvp[32];
#pragma unroll
            for (int g = 0; g < 8; g++)
                *reinterpret_cast<float4*>(&wvp[g * 4]) =
                    *reinterpret_cast<const float4*>(&wsp[(i * 8 + g) * 64 + og * 4]);
#pragma unroll
            for (int ss = 0; ss < 2; ss++) {
                const int s = sg * 2 + ss;
                const float sv = sil[s * 256 + i0 + i];
                const float4* bp = reinterpret_cast<const float4*>(&bas[(s * 32 + i) * 8]);
                float4 bA = bp[0], bB = bp[1];
                float bv[8] = {bA.x, bA.y, bA.z, bA.w, bB.x, bB.y, bB.z, bB.w};
                acc[ss][0] = fmaf(sv, wbv.x, acc[ss][0]);
                acc[ss][1] = fmaf(sv, wbv.y, acc[ss][1]);
                acc[ss][2] = fmaf(sv, wbv.z, acc[ss][2]);
                acc[ss][3] = fmaf(sv, wbv.w, acc[ss][3]);
#pragma unroll
                for (int g = 0; g < 8; g++) {
                    acc[ss][0] = fmaf(bv[g], wvp[g * 4 + 0], acc[ss][0]);
                    acc[ss][1] = fmaf(bv[g], wvp[g * 4 + 1], acc[ss][1]);
                    acc[ss][2] = fmaf(bv[g], wvp[g * 4 + 2], acc[ss][2]);
                    acc[ss][3] = fmaf(bv[g], wvp[g * 4 + 3], acc[ss][3]);
                }
            }
        }
    }

#pragma unroll
    for (int ss = 0; ss < 2; ss++) {
        const int b = b0 + sg * 2 + ss;
        *reinterpret_cast<float4*>(&out[(size_t)b * 64 + og * 4]) =
            make_float4(acc[ss][0], acc[ss][1], acc[ss][2], acc[ss][3]);
    }
}

// ---------------------------------------------------------------------------
// Launch
// ---------------------------------------------------------------------------
extern "C" void kernel_launch(void* const* d_in, const int* in_sizes, int n_in,
                              void* d_out, int out_size)
{
    const float* x    = (const float*)d_in[0];
    const float* w    = (const float*)d_in[1];
    const float* bias = (const float*)d_in[2];
    const float* fc1w = (const float*)d_in[3];
    const float* fc1b = (const float*)d_in[4];
    const float* fc2w = (const float*)d_in[5];
    const float* fc2b = (const float*)d_in[6];
    const float* kbw  = (const float*)d_in[7];
    const float* ksw  = (const float*)d_in[8];
    const float* kss  = (const float*)d_in[9];
    float* out = (float*)d_out;

    cudaFuncSetAttribute(gemm_kernel, cudaFuncAttributeMaxDynamicSharedMemorySize, GEMM_SMEM);
    cudaFuncSetAttribute(kan_kernel,  cudaFuncAttributeMaxDynamicSharedMemorySize, KAN_SMEM_BYTES);

    prep_x_kernel<<<BATCH, 256>>>(x);
    prep_w_kernel<<<NDIM, 256>>>(w);
    attn_kernel<<<BATCH / 16, 256>>>(fc1w, fc1b, fc2w, fc2b);
    gemm_kernel<<<dim3(BATCH / MT, NDIM / NT), 256, GEMM_SMEM>>>(bias);
    kan_kernel<<<BATCH / KBT, 256, KAN_SMEM_BYTES>>>(kbw, ksw, kss, out);
}

// round 7
// speedup vs baseline: 2.1841x; 1.2341x over previous
#include <cuda_runtime.h>
#include <cuda_bf16.h>
#include <math.h>
#include <stdint.h>

#define BATCH 8192
#define CIN   256
#define NK    4
#define COUT  64
#define KD    2304            // exact im2col K = 256 c * 9 ij
#define MROWS (BATCH * 4)     // m = b*4 + p
#define NDIM  256             // n = o*4 + nk
#define KBT   32

// GEMM tiling
#define MT 128
#define NT 128
#define KC 64                 // bf16 per K-chunk = 128 bytes
#define NCHUNK (KD / KC)      // 36

// ---------------------------------------------------------------------------
// Static device scratch
// ---------------------------------------------------------------------------
__device__ __nv_bfloat16 g_X2h[(size_t)MROWS * KD];
__device__ __nv_bfloat16 g_X2l[(size_t)MROWS * KD];
__device__ __nv_bfloat16 g_W2h[(size_t)NDIM * KD];
__device__ __nv_bfloat16 g_W2l[(size_t)NDIM * KD];
__device__ float g_feat[(size_t)BATCH * 256];
__device__ float g_pooled[(size_t)BATCH * CIN];
__device__ float g_attn[(size_t)BATCH * NK];

// ---------------------------------------------------------------------------
// PTX helpers (base ISA only: cp.async, ldmatrix, mma.sync)
// ---------------------------------------------------------------------------
__device__ __forceinline__ unsigned smem_u32(const void* p) {
    unsigned a;
    asm("{ .reg .u64 t; cvta.to.shared.u64 t, %1; cvt.u32.u64 %0, t; }" : "=r"(a) : "l"(p));
    return a;
}
__device__ __forceinline__ void cp_async16(unsigned saddr, const void* g) {
    asm volatile("cp.async.cg.shared.global [%0], [%1], 16;" :: "r"(saddr), "l"(g));
}
#define CP_COMMIT() asm volatile("cp.async.commit_group;" ::: "memory")
#define CP_WAIT2()  asm volatile("cp.async.wait_group 2;" ::: "memory")

#define LDSM_X4(r0, r1, r2, r3, addr) \
    asm volatile("ldmatrix.sync.aligned.m8n8.x4.shared.b16 {%0,%1,%2,%3}, [%4];" \
                 : "=r"(r0), "=r"(r1), "=r"(r2), "=r"(r3) : "r"(addr))

#define MMA16816(c, a, b0, b1) \
    asm volatile("mma.sync.aligned.m16n8k16.row.col.f32.bf16.bf16.f32 " \
                 "{%0,%1,%2,%3}, {%4,%5,%6,%7}, {%8,%9}, {%0,%1,%2,%3};" \
                 : "+f"((c)[0]), "+f"((c)[1]), "+f"((c)[2]), "+f"((c)[3]) \
                 : "r"((a)[0]), "r"((a)[1]), "r"((a)[2]), "r"((a)[3]), \
                   "r"(b0), "r"(b1))

#define SWZ(o) ((o) ^ (((o) >> 3) & 0x70))

// ---------------------------------------------------------------------------
// Prep 1: x fp32 -> im2col X2 hi/lo bf16 + fused GAP.
// Block = one sample. Stage 4 patches in smem, flush coalesced.
// X2[(b*4+p)][ij*256 + c] = x[b, c, (p>>1)+i, (p&1)+j]
// ---------------------------------------------------------------------------
__global__ __launch_bounds__(256) void prep_x_kernel(const float* __restrict__ x)
{
    __shared__ __align__(16) __nv_bfloat16 sh[4 * KD];
    __shared__ __align__(16) __nv_bfloat16 sl[4 * KD];
    const int b = blockIdx.x, c = threadIdx.x;

    const float4* src = reinterpret_cast<const float4*>(x + ((size_t)b * CIN + c) * 16);
    float4 v[4];
#pragma unroll
    for (int i = 0; i < 4; i++) v[i] = src[i];
    const float* f = reinterpret_cast<const float*>(v);

    __nv_bfloat16 h16[16], l16[16];
    float sum = 0.f;
#pragma unroll
    for (int e = 0; e < 16; e++) {
        float fv = f[e];
        sum += fv;
        h16[e] = __float2bfloat16(fv);
        l16[e] = __float2bfloat16(fv - __bfloat162float(h16[e]));
    }
    g_pooled[(size_t)b * CIN + c] = sum * (1.f / 16.f);

#pragma unroll
    for (int p = 0; p < 4; p++) {
        const int ph = p >> 1, pw = p & 1;
#pragma unroll
        for (int i = 0; i < 3; i++)
#pragma unroll
            for (int j = 0; j < 3; j++) {
                const int q = (ph + i) * 4 + (pw + j);
                sh[p * KD + (i * 3 + j) * 256 + c] = h16[q];
                sl[p * KD + (i * 3 + j) * 256 + c] = l16[q];
            }
    }
    __syncthreads();

    // flush: 4*2304 bf16 = 18432 B per array = 1152 uint4
    const uint4* s4h = reinterpret_cast<const uint4*>(sh);
    const uint4* s4l = reinterpret_cast<const uint4*>(sl);
    uint4* dh = reinterpret_cast<uint4*>(g_X2h + (size_t)b * 4 * KD);
    uint4* dl = reinterpret_cast<uint4*>(g_X2l + (size_t)b * 4 * KD);
    for (int t = c; t < 1152; t += 256) {
        dh[t] = s4h[t];
        dl[t] = s4l[t];
    }
}

// ---------------------------------------------------------------------------
// Prep 2: weights -> W2[n][k], n = o*4 + nk, k = ij*256 + c, hi/lo bf16.
// ---------------------------------------------------------------------------
__global__ __launch_bounds__(256) void prep_w_kernel(const float* __restrict__ w)
{
    const int n = blockIdx.x, c = threadIdx.x;
    const int o = n >> 2, nk = n & 3;
    const float* wr = w + ((size_t)(nk * COUT + o) * CIN + c) * 9;
#pragma unroll
    for (int ij = 0; ij < 9; ij++) {
        float val = wr[ij];
        __nv_bfloat16 h = __float2bfloat16(val);
        __nv_bfloat16 l = __float2bfloat16(val - __bfloat162float(h));
        g_W2h[(size_t)n * KD + ij * 256 + c] = h;
        g_W2l[(size_t)n * KD + ij * 256 + c] = l;
    }
}

// ---------------------------------------------------------------------------
// Attention: pooled -> fc1 -> relu -> fc2 -> softmax(/34)
// ---------------------------------------------------------------------------
__global__ __launch_bounds__(256) void attn_kernel(
    const float* __restrict__ fc1w, const float* __restrict__ fc1b,
    const float* __restrict__ fc2w, const float* __restrict__ fc2b)
{
    __shared__ float ps[256];
    __shared__ float hpart[4][64];
    __shared__ float hid[64];
    __shared__ float logit[4];
    __shared__ float w2[256];
    __shared__ float b1[64];
    __shared__ float b2[4];

    const int tid = threadIdx.x;
    w2[tid] = fc2w[tid & 255];
    if (tid < 64) b1[tid] = fc1b[tid];
    if (tid < 4)  b2[tid] = fc2b[tid];

    const int h = tid >> 2;
    const int part = tid & 3;

    for (int s = 0; s < 16; s++) {
        const int b = blockIdx.x * 16 + s;
        __syncthreads();
        ps[tid] = g_pooled[(size_t)b * 256 + tid];
        __syncthreads();
        {
            const float4* wr = reinterpret_cast<const float4*>(fc1w + (size_t)h * 256 + part * 64);
            const float4* pr = reinterpret_cast<const float4*>(ps + part * 64);
            float sum = 0.f;
#pragma unroll
            for (int q = 0; q < 16; q++) {
                float4 a = wr[q]; float4 bb = pr[q];
                sum = fmaf(a.x, bb.x, sum); sum = fmaf(a.y, bb.y, sum);
                sum = fmaf(a.z, bb.z, sum); sum = fmaf(a.w, bb.w, sum);
            }
            hpart[part][h] = sum;
        }
        __syncthreads();
        if (tid < 64)
            hid[tid] = fmaxf(hpart[0][tid] + hpart[1][tid] + hpart[2][tid] + hpart[3][tid] + b1[tid], 0.f);
        __syncthreads();
        if (tid < 4) {
            float sm = 0.f;
#pragma unroll
            for (int k2 = 0; k2 < 64; k2++) sm = fmaf(hid[k2], w2[tid * 64 + k2], sm);
            logit[tid] = (sm + b2[tid]) * (1.0f / 34.0f);
        }
        __syncthreads();
        if (tid == 0) {
            float m  = fmaxf(fmaxf(logit[0], logit[1]), fmaxf(logit[2], logit[3]));
            float e0 = expf(logit[0] - m), e1 = expf(logit[1] - m);
            float e2 = expf(logit[2] - m), e3 = expf(logit[3] - m);
            float inv = 1.f / (e0 + e1 + e2 + e3);
            g_attn[(size_t)b * 4 + 0] = e0 * inv;
            g_attn[(size_t)b * 4 + 1] = e1 * inv;
            g_attn[(size_t)b * 4 + 2] = e2 * inv;
            g_attn[(size_t)b * 4 + 3] = e3 * inv;
        }
    }
}

// ---------------------------------------------------------------------------
// GEMM C[32768, 256] = X2 · W2^T  (bf16 hi/lo 3-pass, fp32 reg accum).
// CTA 128x128, 8 warps (2m x 4n), warp tile 64x32, K-chunk 64, 3-stage cp.async.
// blockIdx.x = n-tile (2), blockIdx.y = m-tile (256): y-adjacent CTAs share A in L2.
// Epilogue: attn-combine across nk (shfl pair) + bias -> g_feat[b][o*4+p].
// ---------------------------------------------------------------------------
#define ST_AH 0
#define ST_AL 16384
#define ST_BH 32768
#define ST_BL 49152
#define ST_SZ 65536
#define GEMM_SMEM (3 * ST_SZ)   // 196608

__global__ __launch_bounds__(256, 1) void gemm_kernel(const float* __restrict__ bias)
{
    extern __shared__ __align__(1024) char smem[];
    __shared__ float bias_s[256];

    const unsigned sb = smem_u32(smem);
    const int tid = threadIdx.x;
    const int wid = tid >> 5, lane = tid & 31;
    const int wm = wid >> 2, wn = wid & 3;
    const int n0 = blockIdx.x * NT;
    const int m0 = blockIdx.y * MT;

    bias_s[tid] = bias[tid];

    const char* Xh = (const char*)g_X2h;
    const char* Xl = (const char*)g_X2l;
    const char* Wh = (const char*)g_W2h;
    const char* Wl = (const char*)g_W2l;

    // chunk loader: 128 A rows + 128 B rows, 8 x 16B segs each -> 16 cp.async/thread
    auto load_chunk = [&](int ch, int stg) {
        const unsigned st = sb + stg * ST_SZ;
        const size_t kb = (size_t)ch * 128;
#pragma unroll
        for (int i = 0; i < 4; i++) {
            int s = tid + i * 256;
            int row = s >> 3, seg = s & 7;
            unsigned so = SWZ(row * 128 + seg * 16);
            size_t ga = (size_t)(m0 + row) * (KD * 2) + kb + seg * 16;
            size_t gb = (size_t)(n0 + row) * (KD * 2) + kb + seg * 16;
            cp_async16(st + ST_AH + so, Xh + ga);
            cp_async16(st + ST_AL + so, Xl + ga);
            cp_async16(st + ST_BH + so, Wh + gb);
            cp_async16(st + ST_BL + so, Wl + gb);
        }
    };

    float cAcc[4][4][4];
#pragma unroll
    for (int m = 0; m < 4; m++)
#pragma unroll
        for (int n = 0; n < 4; n++)
#pragma unroll
            for (int r = 0; r < 4; r++) cAcc[m][n][r] = 0.f;

    load_chunk(0, 0); CP_COMMIT();
    load_chunk(1, 1); CP_COMMIT();
    load_chunk(2, 2); CP_COMMIT();

    const int arow = lane & 15;
    const int aseg = (lane >> 4) << 4;

    for (int ch = 0; ch < NCHUNK; ch++) {
        const int stg = ch % 3;
        const unsigned st = sb + stg * ST_SZ;
        CP_WAIT2();
        __syncthreads();

#pragma unroll
        for (int ks = 0; ks < 4; ks++) {
            const int kb = ks * 32 + aseg;
            unsigned ah[4][4], al[4][4], bh[2][4], bl[2][4];
#pragma unroll
            for (int mt = 0; mt < 4; mt++) {
                int r = wm * 64 + mt * 16 + arow;
                unsigned so = SWZ(r * 128 + kb);
                LDSM_X4(ah[mt][0], ah[mt][1], ah[mt][2], ah[mt][3], st + ST_AH + so);
                LDSM_X4(al[mt][0], al[mt][1], al[mt][2], al[mt][3], st + ST_AL + so);
            }
#pragma unroll
            for (int nt2 = 0; nt2 < 2; nt2++) {
                int r = wn * 32 + nt2 * 16 + arow;
                unsigned so = SWZ(r * 128 + kb);
                LDSM_X4(bh[nt2][0], bh[nt2][1], bh[nt2][2], bh[nt2][3], st + ST_BH + so);
                LDSM_X4(bl[nt2][0], bl[nt2][1], bl[nt2][2], bl[nt2][3], st + ST_BL + so);
            }
#pragma unroll
            for (int mt = 0; mt < 4; mt++)
#pragma unroll
                for (int nt2 = 0; nt2 < 2; nt2++)
#pragma unroll
                    for (int b3 = 0; b3 < 2; b3++) {
                        float* c = cAcc[mt][nt2 * 2 + b3];
                        MMA16816(c, ah[mt], bh[nt2][b3], bh[nt2][b3 + 2]);   // hh
                        MMA16816(c, al[mt], bh[nt2][b3], bh[nt2][b3 + 2]);   // lh
                        MMA16816(c, ah[mt], bl[nt2][b3], bl[nt2][b3 + 2]);   // hl
                    }
        }

        __syncthreads();
        if (ch + 3 < NCHUNK) load_chunk(ch + 3, (ch + 3) % 3);
        CP_COMMIT();
    }

    // ---- epilogue: combine nk via lane-pair shfl, add bias, write g_feat ----
    const int j = lane & 3;
    const int rbase = wm * 64 + (lane >> 2);
#pragma unroll
    for (int mt = 0; mt < 4; mt++) {
#pragma unroll
        for (int h = 0; h < 2; h++) {
            const int m = m0 + rbase + mt * 16 + h * 8;
            const int b = m >> 2, p = m & 3;
            const float4 av = *reinterpret_cast<const float4*>(g_attn + (size_t)b * 4);
            const float a[4] = {av.x, av.y, av.z, av.w};
            const int nkb = (j & 1) * 2;
#pragma unroll
            for (int nt2 = 0; nt2 < 2; nt2++)
#pragma unroll
                for (int b3 = 0; b3 < 2; b3++) {
                    const float* c = cAcc[mt][nt2 * 2 + b3];
                    float partial = a[nkb] * c[h * 2 + 0] + a[nkb + 1] * c[h * 2 + 1];
                    partial += __shfl_xor_sync(0xffffffffu, partial, 1);
                    if ((j & 1) == 0) {
                        const int o = (n0 + wn * 32 + nt2 * 16 + b3 * 8) / 4 + (j >> 1);
                        const float bc = a[0] * bias_s[o] + a[1] * bias_s[64 + o]
                                       + a[2] * bias_s[128 + o] + a[3] * bias_s[192 + o];
                        g_feat[(size_t)b * 256 + o * 4 + p] = partial + bc;
                    }
                }
        }
    }
}

// ---------------------------------------------------------------------------
// B-spline bases, grid matches the reference knots bit-exactly.
// ---------------------------------------------------------------------------
__device__ __forceinline__ void bspline8(float t, float* __restrict__ o8)
{
    float g[12];
#pragma unroll
    for (int j = 0; j < 12; j++)
        g[j] = __fadd_rn(__fmul_rn((float)(j - 3), 0.4f), -1.0f);
    float b[11];
#pragma unroll
    for (int j = 0; j < 11; j++)
        b[j] = (t >= g[j] && t < g[j + 1]) ? 1.0f : 0.0f;
#pragma unroll
    for (int k = 1; k <= 3; k++) {
#pragma unroll
        for (int j = 0; j < 10; j++) {
            if (j < 11 - k) {
                float left  = (t - g[j])         * (1.0f / (g[j + k] - g[j]));
                float right = (g[j + k + 1] - t) * (1.0f / (g[j + k + 1] - g[j + 1]));
                b[j] = left * b[j] + right * b[j + 1];
            }
        }
    }
#pragma unroll
    for (int j = 0; j < 8; j++) o8[j] = b[j];
}

// ---------------------------------------------------------------------------
// KANLinear on g_feat
// ---------------------------------------------------------------------------
#define KAN_SMEM_FLOATS (KBT*256 + KBT*256 + 32*8*64 + 32*64 + KBT*32*8)
#define KAN_SMEM_BYTES  (KAN_SMEM_FLOATS * 4)

__global__ __launch_bounds__(256) void kan_kernel(
    const float* __restrict__ base_w,
    const float* __restrict__ spline_w,
    const float* __restrict__ scaler,
    float* __restrict__ out)
{
    extern __shared__ __align__(16) float sm[];
    float* feat = sm;                   // [32][256]
    float* sil  = feat + KBT * 256;     // [32][256]
    float* wsp  = sil  + KBT * 256;     // [i(32)][g(8)][o(64)]
    float* wb   = wsp  + 32 * 8 * 64;   // [i(32)][o(64)]
    float* bas  = wb   + 32 * 64;       // [s(32)][i(32)][g(8)]

    const int tid = threadIdx.x;
    const int b0  = blockIdx.x * KBT;

    {   // load feat, compute silu
        const int s = tid >> 3, lane = tid & 7;
        const size_t fb = (size_t)(b0 + s) * 256;
#pragma unroll 4
        for (int m = 0; m < 32; m++) {
            int i = m * 8 + lane;
            float f = g_feat[fb + i];
            feat[s * 256 + i] = f;
            sil[s * 256 + i]  = f / (1.f + expf(-f));
        }
    }

    const int og = tid & 15;
    const int sg = tid >> 4;
    float acc[2][4] = {{0.f, 0.f, 0.f, 0.f}, {0.f, 0.f, 0.f, 0.f}};

    for (int ic = 0; ic < 8; ic++) {
        const int i0 = ic * 32;
        __syncthreads();

#pragma unroll
        for (int r = 0; r < 16; r++) {
            int l4 = tid + r * 256;
            int o  = l4 & 63;
            int ig = l4 >> 6;
            int i  = ig >> 1;
            int gh = ig & 1;
            float4 v = reinterpret_cast<const float4*>(spline_w)[((size_t)o * 256 + i0 + i) * 2 + gh];
            float sc = scaler[(size_t)o * 256 + i0 + i];
            int gb = gh * 4;
            wsp[(i * 8 + gb + 0) * 64 + o] = v.x * sc;
            wsp[(i * 8 + gb + 1) * 64 + o] = v.y * sc;
            wsp[(i * 8 + gb + 2) * 64 + o] = v.z * sc;
            wsp[(i * 8 + gb + 3) * 64 + o] = v.w * sc;
        }
#pragma unroll
        for (int r = 0; r < 8; r++) {
            int l = tid + r * 256;
            int o = l & 63;
            int i = l >> 6;
            wb[i * 64 + o] = base_w[(size_t)o * 256 + i0 + i];
        }
#pragma unroll
        for (int r = 0; r < 4; r++) {
            int task = tid + r * 256;
            int s = task >> 5;
            int i = task & 31;
            float bb8[8];
            bspline8(feat[s * 256 + i0 + i], bb8);
            float4* dst = reinterpret_cast<float4*>(&bas[(s * 32 + i) * 8]);
            dst[0] = make_float4(bb8[0], bb8[1], bb8[2], bb8[3]);
            dst[1] = make_float4(bb8[4], bb8[5], bb8[6], bb8[7]);
        }
        __syncthreads();

        for (int i = 0; i < 32; i++) {
            float4 wbv = *reinterpret_cast<const float4*>(&wb[i * 64 + og * 4]);
            float wvp[32];
#pragma unroll
            for (int g = 0; g < 8; g++)
                *reinterpret_cast<float4*>(&wvp[g * 4]) =
                    *reinterpret_cast<const float4*>(&wsp[(i * 8 + g) * 64 + og * 4]);
#pragma unroll
            for (int ss = 0; ss < 2; ss++) {
                const int s = sg * 2 + ss;
                const float sv = sil[s * 256 + i0 + i];
                const float4* bp = reinterpret_cast<const float4*>(&bas[(s * 32 + i) * 8]);
                float4 bA = bp[0], bB = bp[1];
                float bv[8] = {bA.x, bA.y, bA.z, bA.w, bB.x, bB.y, bB.z, bB.w};
                acc[ss][0] = fmaf(sv, wbv.x, acc[ss][0]);
                acc[ss][1] = fmaf(sv, wbv.y, acc[ss][1]);
                acc[ss][2] = fmaf(sv, wbv.z, acc[ss][2]);
                acc[ss][3] = fmaf(sv, wbv.w, acc[ss][3]);
#pragma unroll
                for (int g = 0; g < 8; g++) {
                    acc[ss][0] = fmaf(bv[g], wvp[g * 4 + 0], acc[ss][0]);
                    acc[ss][1] = fmaf(bv[g], wvp[g * 4 + 1], acc[ss][1]);
                    acc[ss][2] = fmaf(bv[g], wvp[g * 4 + 2], acc[ss][2]);
                    acc[ss][3] = fmaf(bv[g], wvp[g * 4 + 3], acc[ss][3]);
                }
            }
        }
    }

#pragma unroll
    for (int ss = 0; ss < 2; ss++) {
        const int b = b0 + sg * 2 + ss;
        *reinterpret_cast<float4*>(&out[(size_t)b * 64 + og * 4]) =
            make_float4(acc[ss][0], acc[ss][1], acc[ss][2], acc[ss][3]);
    }
}

// ---------------------------------------------------------------------------
// Launch
// ---------------------------------------------------------------------------
extern "C" void kernel_launch(void* const* d_in, const int* in_sizes, int n_in,
                              void* d_out, int out_size)
{
    const float* x    = (const float*)d_in[0];
    const float* w    = (const float*)d_in[1];
    const float* bias = (const float*)d_in[2];
    const float* fc1w = (const float*)d_in[3];
    const float* fc1b = (const float*)d_in[4];
    const float* fc2w = (const float*)d_in[5];
    const float* fc2b = (const float*)d_in[6];
    const float* kbw  = (const float*)d_in[7];
    const float* ksw  = (const float*)d_in[8];
    const float* kss  = (const float*)d_in[9];
    float* out = (float*)d_out;

    cudaFuncSetAttribute(gemm_kernel, cudaFuncAttributeMaxDynamicSharedMemorySize, GEMM_SMEM);
    cudaFuncSetAttribute(kan_kernel,  cudaFuncAttributeMaxDynamicSharedMemorySize, KAN_SMEM_BYTES);

    prep_x_kernel<<<BATCH, 256>>>(x);
    prep_w_kernel<<<NDIM, 256>>>(w);
    attn_kernel<<<BATCH / 16, 256>>>(fc1w, fc1b, fc2w, fc2b);
    gemm_kernel<<<dim3(NDIM / NT, MROWS / MT), 256, GEMM_SMEM>>>(bias);
    kan_kernel<<<BATCH / KBT, 256, KAN_SMEM_BYTES>>>(kbw, ksw, kss, out);
}

// round 8
// speedup vs baseline: 2.4040x; 1.1007x over previous
#include <cuda_runtime.h>
#include <cuda_bf16.h>
#include <math.h>
#include <stdint.h>

#define BATCH 8192
#define CIN   256
#define NK    4
#define COUT  64
#define KD    2304            // exact im2col K = 256 c * 9 ij
#define MROWS (BATCH * 4)     // m = b*4 + p
#define NDIM  256             // n = o*4 + nk

// GEMM tiling
#define MT 128
#define NT 128
#define KC 64                 // bf16 per K-chunk = 128 bytes
#define NCHUNK (KD / KC)      // 36

// KAN tiling
#define KBT 64                // samples per block
#define KIC 16                // i per chunk -> 16 chunks

// ---------------------------------------------------------------------------
// Static device scratch
// ---------------------------------------------------------------------------
__device__ __nv_bfloat16 g_X2h[(size_t)MROWS * KD];
__device__ __nv_bfloat16 g_X2l[(size_t)MROWS * KD];
__device__ __nv_bfloat16 g_W2h[(size_t)NDIM * KD];
__device__ __nv_bfloat16 g_W2l[(size_t)NDIM * KD];
__device__ float g_feat[(size_t)BATCH * 256];
__device__ float g_pooled[(size_t)BATCH * CIN];
__device__ float g_attn[(size_t)BATCH * NK];

// ---------------------------------------------------------------------------
// PTX helpers (base ISA only: cp.async, ldmatrix, mma.sync)
// ---------------------------------------------------------------------------
__device__ __forceinline__ unsigned smem_u32(const void* p) {
    unsigned a;
    asm("{ .reg .u64 t; cvta.to.shared.u64 t, %1; cvt.u32.u64 %0, t; }" : "=r"(a) : "l"(p));
    return a;
}
__device__ __forceinline__ void cp_async16(unsigned saddr, const void* g) {
    asm volatile("cp.async.cg.shared.global [%0], [%1], 16;" :: "r"(saddr), "l"(g));
}
#define CP_COMMIT() asm volatile("cp.async.commit_group;" ::: "memory")
#define CP_WAIT2()  asm volatile("cp.async.wait_group 2;" ::: "memory")

#define LDSM_X4(r0, r1, r2, r3, addr) \
    asm volatile("ldmatrix.sync.aligned.m8n8.x4.shared.b16 {%0,%1,%2,%3}, [%4];" \
                 : "=r"(r0), "=r"(r1), "=r"(r2), "=r"(r3) : "r"(addr))

#define MMA16816(c, a, b0, b1) \
    asm volatile("mma.sync.aligned.m16n8k16.row.col.f32.bf16.bf16.f32 " \
                 "{%0,%1,%2,%3}, {%4,%5,%6,%7}, {%8,%9}, {%0,%1,%2,%3};" \
                 : "+f"((c)[0]), "+f"((c)[1]), "+f"((c)[2]), "+f"((c)[3]) \
                 : "r"((a)[0]), "r"((a)[1]), "r"((a)[2]), "r"((a)[3]), \
                   "r"(b0), "r"(b1))

#define SWZ(o) ((o) ^ (((o) >> 3) & 0x70))

// ---------------------------------------------------------------------------
// Prep 1: x fp32 -> im2col X2 hi/lo bf16 + fused GAP.
// ---------------------------------------------------------------------------
__global__ __launch_bounds__(256) void prep_x_kernel(const float* __restrict__ x)
{
    __shared__ __align__(16) __nv_bfloat16 sh[4 * KD];
    __shared__ __align__(16) __nv_bfloat16 sl[4 * KD];
    const int b = blockIdx.x, c = threadIdx.x;

    const float4* src = reinterpret_cast<const float4*>(x + ((size_t)b * CIN + c) * 16);
    float4 v[4];
#pragma unroll
    for (int i = 0; i < 4; i++) v[i] = src[i];
    const float* f = reinterpret_cast<const float*>(v);

    __nv_bfloat16 h16[16], l16[16];
    float sum = 0.f;
#pragma unroll
    for (int e = 0; e < 16; e++) {
        float fv = f[e];
        sum += fv;
        h16[e] = __float2bfloat16(fv);
        l16[e] = __float2bfloat16(fv - __bfloat162float(h16[e]));
    }
    g_pooled[(size_t)b * CIN + c] = sum * (1.f / 16.f);

#pragma unroll
    for (int p = 0; p < 4; p++) {
        const int ph = p >> 1, pw = p & 1;
#pragma unroll
        for (int i = 0; i < 3; i++)
#pragma unroll
            for (int j = 0; j < 3; j++) {
                const int q = (ph + i) * 4 + (pw + j);
                sh[p * KD + (i * 3 + j) * 256 + c] = h16[q];
                sl[p * KD + (i * 3 + j) * 256 + c] = l16[q];
            }
    }
    __syncthreads();

    const uint4* s4h = reinterpret_cast<const uint4*>(sh);
    const uint4* s4l = reinterpret_cast<const uint4*>(sl);
    uint4* dh = reinterpret_cast<uint4*>(g_X2h + (size_t)b * 4 * KD);
    uint4* dl = reinterpret_cast<uint4*>(g_X2l + (size_t)b * 4 * KD);
    for (int t = c; t < 1152; t += 256) {
        dh[t] = s4h[t];
        dl[t] = s4l[t];
    }
}

// ---------------------------------------------------------------------------
// Prep 2: weights -> W2[n][k], n = o*4 + nk, k = ij*256 + c, hi/lo bf16.
// ---------------------------------------------------------------------------
__global__ __launch_bounds__(256) void prep_w_kernel(const float* __restrict__ w)
{
    const int n = blockIdx.x, c = threadIdx.x;
    const int o = n >> 2, nk = n & 3;
    const float* wr = w + ((size_t)(nk * COUT + o) * CIN + c) * 9;
#pragma unroll
    for (int ij = 0; ij < 9; ij++) {
        float val = wr[ij];
        __nv_bfloat16 h = __float2bfloat16(val);
        __nv_bfloat16 l = __float2bfloat16(val - __bfloat162float(h));
        g_W2h[(size_t)n * KD + ij * 256 + c] = h;
        g_W2l[(size_t)n * KD + ij * 256 + c] = l;
    }
}

// ---------------------------------------------------------------------------
// Attention: pooled -> fc1 -> relu -> fc2 -> softmax(/34)
// ---------------------------------------------------------------------------
__global__ __launch_bounds__(256) void attn_kernel(
    const float* __restrict__ fc1w, const float* __restrict__ fc1b,
    const float* __restrict__ fc2w, const float* __restrict__ fc2b)
{
    __shared__ float ps[256];
    __shared__ float hpart[4][64];
    __shared__ float hid[64];
    __shared__ float logit[4];
    __shared__ float w2[256];
    __shared__ float b1[64];
    __shared__ float b2[4];

    const int tid = threadIdx.x;
    w2[tid] = fc2w[tid & 255];
    if (tid < 64) b1[tid] = fc1b[tid];
    if (tid < 4)  b2[tid] = fc2b[tid];

    const int h = tid >> 2;
    const int part = tid & 3;

    for (int s = 0; s < 16; s++) {
        const int b = blockIdx.x * 16 + s;
        __syncthreads();
        ps[tid] = g_pooled[(size_t)b * 256 + tid];
        __syncthreads();
        {
            const float4* wr = reinterpret_cast<const float4*>(fc1w + (size_t)h * 256 + part * 64);
            const float4* pr = reinterpret_cast<const float4*>(ps + part * 64);
            float sum = 0.f;
#pragma unroll
            for (int q = 0; q < 16; q++) {
                float4 a = wr[q]; float4 bb = pr[q];
                sum = fmaf(a.x, bb.x, sum); sum = fmaf(a.y, bb.y, sum);
                sum = fmaf(a.z, bb.z, sum); sum = fmaf(a.w, bb.w, sum);
            }
            hpart[part][h] = sum;
        }
        __syncthreads();
        if (tid < 64)
            hid[tid] = fmaxf(hpart[0][tid] + hpart[1][tid] + hpart[2][tid] + hpart[3][tid] + b1[tid], 0.f);
        __syncthreads();
        if (tid < 4) {
            float sm = 0.f;
#pragma unroll
            for (int k2 = 0; k2 < 64; k2++) sm = fmaf(hid[k2], w2[tid * 64 + k2], sm);
            logit[tid] = (sm + b2[tid]) * (1.0f / 34.0f);
        }
        __syncthreads();
        if (tid == 0) {
            float m  = fmaxf(fmaxf(logit[0], logit[1]), fmaxf(logit[2], logit[3]));
            float e0 = expf(logit[0] - m), e1 = expf(logit[1] - m);
            float e2 = expf(logit[2] - m), e3 = expf(logit[3] - m);
            float inv = 1.f / (e0 + e1 + e2 + e3);
            g_attn[(size_t)b * 4 + 0] = e0 * inv;
            g_attn[(size_t)b * 4 + 1] = e1 * inv;
            g_attn[(size_t)b * 4 + 2] = e2 * inv;
            g_attn[(size_t)b * 4 + 3] = e3 * inv;
        }
    }
}

// ---------------------------------------------------------------------------
// GEMM C[32768, 256] = X2 · W2^T  (bf16 hi/lo 3-pass, fp32 reg accum).
// Pass-major MMA order: 16 independent MMAs between accumulator reuse.
// ---------------------------------------------------------------------------
#define ST_AH 0
#define ST_AL 16384
#define ST_BH 32768
#define ST_BL 49152
#define ST_SZ 65536
#define GEMM_SMEM (3 * ST_SZ)   // 196608

__global__ __launch_bounds__(256, 1) void gemm_kernel(const float* __restrict__ bias)
{
    extern __shared__ __align__(1024) char smem[];
    __shared__ float bias_s[256];

    const unsigned sb = smem_u32(smem);
    const int tid = threadIdx.x;
    const int wid = tid >> 5, lane = tid & 31;
    const int wm = wid >> 2, wn = wid & 3;
    const int n0 = blockIdx.x * NT;
    const int m0 = blockIdx.y * MT;

    bias_s[tid] = bias[tid];

    const char* Xh = (const char*)g_X2h;
    const char* Xl = (const char*)g_X2l;
    const char* Wh = (const char*)g_W2h;
    const char* Wl = (const char*)g_W2l;

    auto load_chunk = [&](int ch, int stg) {
        const unsigned st = sb + stg * ST_SZ;
        const size_t kb = (size_t)ch * 128;
#pragma unroll
        for (int i = 0; i < 4; i++) {
            int s = tid + i * 256;
            int row = s >> 3, seg = s & 7;
            unsigned so = SWZ(row * 128 + seg * 16);
            size_t ga = (size_t)(m0 + row) * (KD * 2) + kb + seg * 16;
            size_t gb = (size_t)(n0 + row) * (KD * 2) + kb + seg * 16;
            cp_async16(st + ST_AH + so, Xh + ga);
            cp_async16(st + ST_AL + so, Xl + ga);
            cp_async16(st + ST_BH + so, Wh + gb);
            cp_async16(st + ST_BL + so, Wl + gb);
        }
    };

    float cAcc[4][4][4];
#pragma unroll
    for (int m = 0; m < 4; m++)
#pragma unroll
        for (int n = 0; n < 4; n++)
#pragma unroll
            for (int r = 0; r < 4; r++) cAcc[m][n][r] = 0.f;

    load_chunk(0, 0); CP_COMMIT();
    load_chunk(1, 1); CP_COMMIT();
    load_chunk(2, 2); CP_COMMIT();

    const int arow = lane & 15;
    const int aseg = (lane >> 4) << 4;

    for (int ch = 0; ch < NCHUNK; ch++) {
        const int stg = ch % 3;
        const unsigned st = sb + stg * ST_SZ;
        CP_WAIT2();
        __syncthreads();

#pragma unroll
        for (int ks = 0; ks < 4; ks++) {
            const int kb = ks * 32 + aseg;
            unsigned ah[4][4], al[4][4], bh[2][4], bl[2][4];
#pragma unroll
            for (int mt = 0; mt < 4; mt++) {
                int r = wm * 64 + mt * 16 + arow;
                unsigned so = SWZ(r * 128 + kb);
                LDSM_X4(ah[mt][0], ah[mt][1], ah[mt][2], ah[mt][3], st + ST_AH + so);
                LDSM_X4(al[mt][0], al[mt][1], al[mt][2], al[mt][3], st + ST_AL + so);
            }
#pragma unroll
            for (int nt2 = 0; nt2 < 2; nt2++) {
                int r = wn * 32 + nt2 * 16 + arow;
                unsigned so = SWZ(r * 128 + kb);
                LDSM_X4(bh[nt2][0], bh[nt2][1], bh[nt2][2], bh[nt2][3], st + ST_BH + so);
                LDSM_X4(bl[nt2][0], bl[nt2][1], bl[nt2][2], bl[nt2][3], st + ST_BL + so);
            }
            // pass-major: all 16 independent MMAs per pass, then next pass
#pragma unroll
            for (int mt = 0; mt < 4; mt++)
#pragma unroll
                for (int nt2 = 0; nt2 < 2; nt2++)
#pragma unroll
                    for (int b3 = 0; b3 < 2; b3++)
                        MMA16816(cAcc[mt][nt2 * 2 + b3], ah[mt], bh[nt2][b3], bh[nt2][b3 + 2]);
#pragma unroll
            for (int mt = 0; mt < 4; mt++)
#pragma unroll
                for (int nt2 = 0; nt2 < 2; nt2++)
#pragma unroll
                    for (int b3 = 0; b3 < 2; b3++)
                        MMA16816(cAcc[mt][nt2 * 2 + b3], al[mt], bh[nt2][b3], bh[nt2][b3 + 2]);
#pragma unroll
            for (int mt = 0; mt < 4; mt++)
#pragma unroll
                for (int nt2 = 0; nt2 < 2; nt2++)
#pragma unroll
                    for (int b3 = 0; b3 < 2; b3++)
                        MMA16816(cAcc[mt][nt2 * 2 + b3], ah[mt], bl[nt2][b3], bl[nt2][b3 + 2]);
        }

        __syncthreads();
        if (ch + 3 < NCHUNK) load_chunk(ch + 3, (ch + 3) % 3);
        CP_COMMIT();
    }

    // ---- epilogue: combine nk via lane-pair shfl, add bias, write g_feat ----
    const int j = lane & 3;
    const int rbase = wm * 64 + (lane >> 2);
#pragma unroll
    for (int mt = 0; mt < 4; mt++) {
#pragma unroll
        for (int h = 0; h < 2; h++) {
            const int m = m0 + rbase + mt * 16 + h * 8;
            const int b = m >> 2, p = m & 3;
            const float4 av = *reinterpret_cast<const float4*>(g_attn + (size_t)b * 4);
            const float a[4] = {av.x, av.y, av.z, av.w};
            const int nkb = (j & 1) * 2;
#pragma unroll
            for (int nt2 = 0; nt2 < 2; nt2++)
#pragma unroll
                for (int b3 = 0; b3 < 2; b3++) {
                    const float* c = cAcc[mt][nt2 * 2 + b3];
                    float partial = a[nkb] * c[h * 2 + 0] + a[nkb + 1] * c[h * 2 + 1];
                    partial += __shfl_xor_sync(0xffffffffu, partial, 1);
                    if ((j & 1) == 0) {
                        const int o = (n0 + wn * 32 + nt2 * 16 + b3 * 8) / 4 + (j >> 1);
                        const float bc = a[0] * bias_s[o] + a[1] * bias_s[64 + o]
                                       + a[2] * bias_s[128 + o] + a[3] * bias_s[192 + o];
                        g_feat[(size_t)b * 256 + o * 4 + p] = partial + bc;
                    }
                }
        }
    }
}

// ---------------------------------------------------------------------------
// B-spline bases, grid matches the reference knots bit-exactly.
// ---------------------------------------------------------------------------
__device__ __forceinline__ void bspline8(float t, float* __restrict__ o8)
{
    float g[12];
#pragma unroll
    for (int j = 0; j < 12; j++)
        g[j] = __fadd_rn(__fmul_rn((float)(j - 3), 0.4f), -1.0f);
    float b[11];
#pragma unroll
    for (int j = 0; j < 11; j++)
        b[j] = (t >= g[j] && t < g[j + 1]) ? 1.0f : 0.0f;
#pragma unroll
    for (int k = 1; k <= 3; k++) {
#pragma unroll
        for (int j = 0; j < 10; j++) {
            if (j < 11 - k) {
                float left  = (t - g[j])         * (1.0f / (g[j + k] - g[j]));
                float right = (g[j + k + 1] - t) * (1.0f / (g[j + k + 1] - g[j + 1]));
                b[j] = left * b[j] + right * b[j + 1];
            }
        }
    }
#pragma unroll
    for (int j = 0; j < 8; j++) o8[j] = b[j];
}

// ---------------------------------------------------------------------------
// KANLinear: KBT=64 samples/block, i-chunk 16, thread tile 4 samples x 4 outputs.
// ---------------------------------------------------------------------------
#define KAN_SMEM_FLOATS (KBT*256*2 + KIC*8*64 + KIC*64 + KBT*KIC*8)
#define KAN_SMEM_BYTES  (KAN_SMEM_FLOATS * 4)   // 200704

__global__ __launch_bounds__(256) void kan_kernel(
    const float* __restrict__ base_w,
    const float* __restrict__ spline_w,
    const float* __restrict__ scaler,
    float* __restrict__ out)
{
    extern __shared__ __align__(16) float sm[];
    float* feat = sm;                     // [64][256]
    float* sil  = feat + KBT * 256;       // [64][256]
    float* wsp  = sil  + KBT * 256;       // [i(16)][g(8)][o(64)]
    float* wb   = wsp  + KIC * 8 * 64;    // [i(16)][o(64)]
    float* bas  = wb   + KIC * 64;        // [s(64)][i(16)][g(8)]

    const int tid = threadIdx.x;
    const int b0  = blockIdx.x * KBT;

    {   // load feat (float4-coalesced), compute silu
        const float4* src = reinterpret_cast<const float4*>(g_feat + (size_t)b0 * 256);
#pragma unroll 4
        for (int r = 0; r < 16; r++) {
            int idx4 = tid + r * 256;
            float4 v = src[idx4];
            *reinterpret_cast<float4*>(&feat[idx4 * 4]) = v;
            float4 s;
            s.x = v.x / (1.f + expf(-v.x));
            s.y = v.y / (1.f + expf(-v.y));
            s.z = v.z / (1.f + expf(-v.z));
            s.w = v.w / (1.f + expf(-v.w));
            *reinterpret_cast<float4*>(&sil[idx4 * 4]) = s;
        }
    }

    const int og = tid & 15;      // outputs og*4 .. +3
    const int sg = tid >> 4;      // samples sg*4 .. +3
    float acc[4][4];
#pragma unroll
    for (int ss = 0; ss < 4; ss++)
#pragma unroll
        for (int r = 0; r < 4; r++) acc[ss][r] = 0.f;

    for (int ic = 0; ic < 16; ic++) {
        const int i0 = ic * KIC;
        __syncthreads();

        // spline weights (pre-scaled), transposed to [i][g][o]: 8192 floats
#pragma unroll
        for (int r = 0; r < 8; r++) {
            int l4 = tid + r * 256;
            int o  = l4 & 63;
            int ig = l4 >> 6;        // 0..31
            int i  = ig >> 1;
            int gh = ig & 1;
            float4 v = reinterpret_cast<const float4*>(spline_w)[((size_t)o * 256 + i0 + i) * 2 + gh];
            float sc = scaler[(size_t)o * 256 + i0 + i];
            int gb = gh * 4;
            wsp[(i * 8 + gb + 0) * 64 + o] = v.x * sc;
            wsp[(i * 8 + gb + 1) * 64 + o] = v.y * sc;
            wsp[(i * 8 + gb + 2) * 64 + o] = v.z * sc;
            wsp[(i * 8 + gb + 3) * 64 + o] = v.w * sc;
        }
        // base weights chunk [i][o]: 1024 floats
        {
            int l = tid + 0 * 256;
            int o = l & 63;
            int i = l >> 6;
            wb[i * 64 + o] = base_w[(size_t)o * 256 + i0 + i];
            l = tid + 256;
            o = l & 63; i = l >> 6;
            wb[i * 64 + o] = base_w[(size_t)o * 256 + i0 + i];
            l = tid + 512;
            o = l & 63; i = l >> 6;
            wb[i * 64 + o] = base_w[(size_t)o * 256 + i0 + i];
            l = tid + 768;
            o = l & 63; i = l >> 6;
            wb[i * 64 + o] = base_w[(size_t)o * 256 + i0 + i];
        }
        // bases chunk: 64 s x 16 i = 1024 bspline evals
#pragma unroll
        for (int r = 0; r < 4; r++) {
            int task = tid + r * 256;
            int s = task >> 4;
            int i = task & 15;
            float bb8[8];
            bspline8(feat[s * 256 + i0 + i], bb8);
            float4* dst = reinterpret_cast<float4*>(&bas[(s * KIC + i) * 8]);
            dst[0] = make_float4(bb8[0], bb8[1], bb8[2], bb8[3]);
            dst[1] = make_float4(bb8[4], bb8[5], bb8[6], bb8[7]);
        }
        __syncthreads();

        for (int i = 0; i < KIC; i++) {
            float4 wbv = *reinterpret_cast<const float4*>(&wb[i * 64 + og * 4]);
            float wvp[32];
#pragma unroll
            for (int g = 0; g < 8; g++)
                *reinterpret_cast<float4*>(&wvp[g * 4]) =
                    *reinterpret_cast<const float4*>(&wsp[(i * 8 + g) * 64 + og * 4]);
#pragma unroll
            for (int ss = 0; ss < 4; ss++) {
                const int s = sg * 4 + ss;
                const float sv = sil[s * 256 + i0 + i];
                const float4* bp = reinterpret_cast<const float4*>(&bas[(s * KIC + i) * 8]);
                float4 bA = bp[0], bB = bp[1];
                float bv[8] = {bA.x, bA.y, bA.z, bA.w, bB.x, bB.y, bB.z, bB.w};
                acc[ss][0] = fmaf(sv, wbv.x, acc[ss][0]);
                acc[ss][1] = fmaf(sv, wbv.y, acc[ss][1]);
                acc[ss][2] = fmaf(sv, wbv.z, acc[ss][2]);
                acc[ss][3] = fmaf(sv, wbv.w, acc[ss][3]);
#pragma unroll
                for (int g = 0; g < 8; g++) {
                    acc[ss][0] = fmaf(bv[g], wvp[g * 4 + 0], acc[ss][0]);
                    acc[ss][1] = fmaf(bv[g], wvp[g * 4 + 1], acc[ss][1]);
                    acc[ss][2] = fmaf(bv[g], wvp[g * 4 + 2], acc[ss][2]);
                    acc[ss][3] = fmaf(bv[g], wvp[g * 4 + 3], acc[ss][3]);
                }
            }
        }
    }

#pragma unroll
    for (int ss = 0; ss < 4; ss++) {
        const int b = b0 + sg * 4 + ss;
        *reinterpret_cast<float4*>(&out[(size_t)b * 64 + og * 4]) =
            make_float4(acc[ss][0], acc[ss][1], acc[ss][2], acc[ss][3]);
    }
}

// ---------------------------------------------------------------------------
// Launch
// ---------------------------------------------------------------------------
extern "C" void kernel_launch(void* const* d_in, const int* in_sizes, int n_in,
                              void* d_out, int out_size)
{
    const float* x    = (const float*)d_in[0];
    const float* w    = (const float*)d_in[1];
    const float* bias = (const float*)d_in[2];
    const float* fc1w = (const float*)d_in[3];
    const float* fc1b = (const float*)d_in[4];
    const float* fc2w = (const float*)d_in[5];
    const float* fc2b = (const float*)d_in[6];
    const float* kbw  = (const float*)d_in[7];
    const float* ksw  = (const float*)d_in[8];
    const float* kss  = (const float*)d_in[9];
    float* out = (float*)d_out;

    cudaFuncSetAttribute(gemm_kernel, cudaFuncAttributeMaxDynamicSharedMemorySize, GEMM_SMEM);
    cudaFuncSetAttribute(kan_kernel,  cudaFuncAttributeMaxDynamicSharedMemorySize, KAN_SMEM_BYTES);

    prep_x_kernel<<<BATCH, 256>>>(x);
    prep_w_kernel<<<NDIM, 256>>>(w);
    attn_kernel<<<BATCH / 16, 256>>>(fc1w, fc1b, fc2w, fc2b);
    gemm_kernel<<<dim3(NDIM / NT, MROWS / MT), 256, GEMM_SMEM>>>(bias);
    kan_kernel<<<BATCH / KBT, 256, KAN_SMEM_BYTES>>>(kbw, ksw, kss, out);
}

// round 9
// speedup vs baseline: 2.6844x; 1.1166x over previous
#include <cuda_runtime.h>
#include <cuda_bf16.h>
#include <math.h>
#include <stdint.h>

#define BATCH 8192
#define CIN   256
#define NK    4
#define COUT  64
#define KD    2304            // exact im2col K = 256 c * 9 ij
#define MROWS (BATCH * 4)     // m = b*4 + p
#define NDIM  256             // n = o*4 + nk

// GEMM tiling
#define MT 128
#define NT 64
#define KC 64                 // bf16 per K-chunk = 128 bytes
#define NCHUNK (KD / KC)      // 36

// KAN tiling
#define KBT 64
#define KIC 16

// ---------------------------------------------------------------------------
// Static device scratch
// ---------------------------------------------------------------------------
__device__ __nv_bfloat16 g_X2h[(size_t)MROWS * KD];
__device__ __nv_bfloat16 g_X2l[(size_t)MROWS * KD];
__device__ __nv_bfloat16 g_W2h[(size_t)NDIM * KD];
__device__ __nv_bfloat16 g_W2l[(size_t)NDIM * KD];
__device__ float g_feat[(size_t)BATCH * 256];
__device__ float g_pooled[(size_t)BATCH * CIN];
__device__ float g_attn[(size_t)BATCH * NK];

// ---------------------------------------------------------------------------
// PTX helpers
// ---------------------------------------------------------------------------
__device__ __forceinline__ unsigned smem_u32(const void* p) {
    unsigned a;
    asm("{ .reg .u64 t; cvta.to.shared.u64 t, %1; cvt.u32.u64 %0, t; }" : "=r"(a) : "l"(p));
    return a;
}
__device__ __forceinline__ void cp_async16(unsigned saddr, const void* g) {
    asm volatile("cp.async.cg.shared.global [%0], [%1], 16;" :: "r"(saddr), "l"(g));
}
#define CP_COMMIT() asm volatile("cp.async.commit_group;" ::: "memory")
#define CP_WAIT1()  asm volatile("cp.async.wait_group 1;" ::: "memory")

#define LDSM_X4(r0, r1, r2, r3, addr) \
    asm volatile("ldmatrix.sync.aligned.m8n8.x4.shared.b16 {%0,%1,%2,%3}, [%4];" \
                 : "=r"(r0), "=r"(r1), "=r"(r2), "=r"(r3) : "r"(addr))

#define MMA16816(c, a, b0, b1) \
    asm volatile("mma.sync.aligned.m16n8k16.row.col.f32.bf16.bf16.f32 " \
                 "{%0,%1,%2,%3}, {%4,%5,%6,%7}, {%8,%9}, {%0,%1,%2,%3};" \
                 : "+f"((c)[0]), "+f"((c)[1]), "+f"((c)[2]), "+f"((c)[3]) \
                 : "r"((a)[0]), "r"((a)[1]), "r"((a)[2]), "r"((a)[3]), \
                   "r"(b0), "r"(b1))

#define SWZ(o) ((o) ^ (((o) >> 3) & 0x70))

// ---------------------------------------------------------------------------
// Prep 1: x fp32 -> im2col X2 hi/lo bf16 + fused GAP.
// ---------------------------------------------------------------------------
__global__ __launch_bounds__(256) void prep_x_kernel(const float* __restrict__ x)
{
    __shared__ __align__(16) __nv_bfloat16 sh[4 * KD];
    __shared__ __align__(16) __nv_bfloat16 sl[4 * KD];
    const int b = blockIdx.x, c = threadIdx.x;

    const float4* src = reinterpret_cast<const float4*>(x + ((size_t)b * CIN + c) * 16);
    float4 v[4];
#pragma unroll
    for (int i = 0; i < 4; i++) v[i] = src[i];
    const float* f = reinterpret_cast<const float*>(v);

    __nv_bfloat16 h16[16], l16[16];
    float sum = 0.f;
#pragma unroll
    for (int e = 0; e < 16; e++) {
        float fv = f[e];
        sum += fv;
        h16[e] = __float2bfloat16(fv);
        l16[e] = __float2bfloat16(fv - __bfloat162float(h16[e]));
    }
    g_pooled[(size_t)b * CIN + c] = sum * (1.f / 16.f);

#pragma unroll
    for (int p = 0; p < 4; p++) {
        const int ph = p >> 1, pw = p & 1;
#pragma unroll
        for (int i = 0; i < 3; i++)
#pragma unroll
            for (int j = 0; j < 3; j++) {
                const int q = (ph + i) * 4 + (pw + j);
                sh[p * KD + (i * 3 + j) * 256 + c] = h16[q];
                sl[p * KD + (i * 3 + j) * 256 + c] = l16[q];
            }
    }
    __syncthreads();

    const uint4* s4h = reinterpret_cast<const uint4*>(sh);
    const uint4* s4l = reinterpret_cast<const uint4*>(sl);
    uint4* dh = reinterpret_cast<uint4*>(g_X2h + (size_t)b * 4 * KD);
    uint4* dl = reinterpret_cast<uint4*>(g_X2l + (size_t)b * 4 * KD);
    for (int t = c; t < 1152; t += 256) {
        dh[t] = s4h[t];
        dl[t] = s4l[t];
    }
}

// ---------------------------------------------------------------------------
// Prep 2: weights -> W2[n][k], n = o*4 + nk, k = ij*256 + c, hi/lo bf16.
// ---------------------------------------------------------------------------
__global__ __launch_bounds__(256) void prep_w_kernel(const float* __restrict__ w)
{
    const int n = blockIdx.x, c = threadIdx.x;
    const int o = n >> 2, nk = n & 3;
    const float* wr = w + ((size_t)(nk * COUT + o) * CIN + c) * 9;
#pragma unroll
    for (int ij = 0; ij < 9; ij++) {
        float val = wr[ij];
        __nv_bfloat16 h = __float2bfloat16(val);
        __nv_bfloat16 l = __float2bfloat16(val - __bfloat162float(h));
        g_W2h[(size_t)n * KD + ij * 256 + c] = h;
        g_W2l[(size_t)n * KD + ij * 256 + c] = l;
    }
}

// ---------------------------------------------------------------------------
// Attention: pooled -> fc1 -> relu -> fc2 -> softmax(/34)
// ---------------------------------------------------------------------------
__global__ __launch_bounds__(256) void attn_kernel(
    const float* __restrict__ fc1w, const float* __restrict__ fc1b,
    const float* __restrict__ fc2w, const float* __restrict__ fc2b)
{
    __shared__ float ps[256];
    __shared__ float hpart[4][64];
    __shared__ float hid[64];
    __shared__ float logit[4];
    __shared__ float w2[256];
    __shared__ float b1[64];
    __shared__ float b2[4];

    const int tid = threadIdx.x;
    w2[tid] = fc2w[tid & 255];
    if (tid < 64) b1[tid] = fc1b[tid];
    if (tid < 4)  b2[tid] = fc2b[tid];

    const int h = tid >> 2;
    const int part = tid & 3;

    for (int s = 0; s < 16; s++) {
        const int b = blockIdx.x * 16 + s;
        __syncthreads();
        ps[tid] = g_pooled[(size_t)b * 256 + tid];
        __syncthreads();
        {
            const float4* wr = reinterpret_cast<const float4*>(fc1w + (size_t)h * 256 + part * 64);
            const float4* pr = reinterpret_cast<const float4*>(ps + part * 64);
            float sum = 0.f;
#pragma unroll
            for (int q = 0; q < 16; q++) {
                float4 a = wr[q]; float4 bb = pr[q];
                sum = fmaf(a.x, bb.x, sum); sum = fmaf(a.y, bb.y, sum);
                sum = fmaf(a.z, bb.z, sum); sum = fmaf(a.w, bb.w, sum);
            }
            hpart[part][h] = sum;
        }
        __syncthreads();
        if (tid < 64)
            hid[tid] = fmaxf(hpart[0][tid] + hpart[1][tid] + hpart[2][tid] + hpart[3][tid] + b1[tid], 0.f);
        __syncthreads();
        if (tid < 4) {
            float sm = 0.f;
#pragma unroll
            for (int k2 = 0; k2 < 64; k2++) sm = fmaf(hid[k2], w2[tid * 64 + k2], sm);
            logit[tid] = (sm + b2[tid]) * (1.0f / 34.0f);
        }
        __syncthreads();
        if (tid == 0) {
            float m  = fmaxf(fmaxf(logit[0], logit[1]), fmaxf(logit[2], logit[3]));
            float e0 = expf(logit[0] - m), e1 = expf(logit[1] - m);
            float e2 = expf(logit[2] - m), e3 = expf(logit[3] - m);
            float inv = 1.f / (e0 + e1 + e2 + e3);
            g_attn[(size_t)b * 4 + 0] = e0 * inv;
            g_attn[(size_t)b * 4 + 1] = e1 * inv;
            g_attn[(size_t)b * 4 + 2] = e2 * inv;
            g_attn[(size_t)b * 4 + 3] = e3 * inv;
        }
    }
}

// ---------------------------------------------------------------------------
// GEMM C[32768, 256] = X2 · W2^T  (bf16 hi/lo 3-pass, fp32 reg accum).
// CTA 128x64, 8 warps (4m x 2n), warp tile 32x32, 2-stage, 2 CTAs/SM.
// ---------------------------------------------------------------------------
#define ST_AH 0
#define ST_AL 16384
#define ST_BH 32768
#define ST_BL 40960
#define ST_SZ 49152
#define GEMM_SMEM (2 * ST_SZ)   // 98304

__global__ __launch_bounds__(256, 2) void gemm_kernel(const float* __restrict__ bias)
{
    extern __shared__ __align__(1024) char smem[];
    __shared__ float bias_s[256];

    const unsigned sb = smem_u32(smem);
    const int tid = threadIdx.x;
    const int wid = tid >> 5, lane = tid & 31;
    const int wm = wid >> 1, wn = wid & 1;
    const int n0 = blockIdx.x * NT;
    const int m0 = blockIdx.y * MT;

    bias_s[tid] = bias[tid];

    const char* Xh = (const char*)g_X2h;
    const char* Xl = (const char*)g_X2l;
    const char* Wh = (const char*)g_W2h;
    const char* Wl = (const char*)g_W2l;

    // chunk loader: A 128 rows, B 64 rows, 8 x 16B segs each
    auto load_chunk = [&](int ch, int stg) {
        const unsigned st = sb + stg * ST_SZ;
        const size_t kb = (size_t)ch * 128;
#pragma unroll
        for (int i = 0; i < 4; i++) {
            int s = tid + i * 256;
            int row = s >> 3, seg = s & 7;
            unsigned so = SWZ(row * 128 + seg * 16);
            size_t ga = (size_t)(m0 + row) * (KD * 2) + kb + seg * 16;
            cp_async16(st + ST_AH + so, Xh + ga);
            cp_async16(st + ST_AL + so, Xl + ga);
        }
#pragma unroll
        for (int i = 0; i < 2; i++) {
            int s = tid + i * 256;
            int row = s >> 3, seg = s & 7;
            unsigned so = SWZ(row * 128 + seg * 16);
            size_t gb = (size_t)(n0 + row) * (KD * 2) + kb + seg * 16;
            cp_async16(st + ST_BH + so, Wh + gb);
            cp_async16(st + ST_BL + so, Wl + gb);
        }
    };

    float cAcc[2][4][4];
#pragma unroll
    for (int m = 0; m < 2; m++)
#pragma unroll
        for (int n = 0; n < 4; n++)
#pragma unroll
            for (int r = 0; r < 4; r++) cAcc[m][n][r] = 0.f;

    load_chunk(0, 0); CP_COMMIT();
    load_chunk(1, 1); CP_COMMIT();

    const int arow = lane & 15;
    const int aseg = (lane >> 4) << 4;

    for (int ch = 0; ch < NCHUNK; ch++) {
        const int stg = ch & 1;
        const unsigned st = sb + stg * ST_SZ;
        CP_WAIT1();
        __syncthreads();

#pragma unroll
        for (int ks = 0; ks < 4; ks++) {
            const int kb = ks * 32 + aseg;
            unsigned ah[2][4], al[2][4], bh[2][4], bl[2][4];
#pragma unroll
            for (int mt = 0; mt < 2; mt++) {
                int r = wm * 32 + mt * 16 + arow;
                unsigned so = SWZ(r * 128 + kb);
                LDSM_X4(ah[mt][0], ah[mt][1], ah[mt][2], ah[mt][3], st + ST_AH + so);
                LDSM_X4(al[mt][0], al[mt][1], al[mt][2], al[mt][3], st + ST_AL + so);
            }
#pragma unroll
            for (int nt2 = 0; nt2 < 2; nt2++) {
                int r = wn * 32 + nt2 * 16 + arow;
                unsigned so = SWZ(r * 128 + kb);
                LDSM_X4(bh[nt2][0], bh[nt2][1], bh[nt2][2], bh[nt2][3], st + ST_BH + so);
                LDSM_X4(bl[nt2][0], bl[nt2][1], bl[nt2][2], bl[nt2][3], st + ST_BL + so);
            }
#pragma unroll
            for (int mt = 0; mt < 2; mt++)
#pragma unroll
                for (int nt2 = 0; nt2 < 2; nt2++)
#pragma unroll
                    for (int b3 = 0; b3 < 2; b3++)
                        MMA16816(cAcc[mt][nt2 * 2 + b3], ah[mt], bh[nt2][b3], bh[nt2][b3 + 2]);
#pragma unroll
            for (int mt = 0; mt < 2; mt++)
#pragma unroll
                for (int nt2 = 0; nt2 < 2; nt2++)
#pragma unroll
                    for (int b3 = 0; b3 < 2; b3++)
                        MMA16816(cAcc[mt][nt2 * 2 + b3], al[mt], bh[nt2][b3], bh[nt2][b3 + 2]);
#pragma unroll
            for (int mt = 0; mt < 2; mt++)
#pragma unroll
                for (int nt2 = 0; nt2 < 2; nt2++)
#pragma unroll
                    for (int b3 = 0; b3 < 2; b3++)
                        MMA16816(cAcc[mt][nt2 * 2 + b3], ah[mt], bl[nt2][b3], bl[nt2][b3 + 2]);
        }

        __syncthreads();
        if (ch + 2 < NCHUNK) load_chunk(ch + 2, stg);
        CP_COMMIT();
    }

    // ---- epilogue: combine nk via lane-pair shfl, add bias, write g_feat ----
    const int j = lane & 3;
    const int rbase = wm * 32 + (lane >> 2);
#pragma unroll
    for (int mt = 0; mt < 2; mt++) {
#pragma unroll
        for (int h = 0; h < 2; h++) {
            const int m = m0 + rbase + mt * 16 + h * 8;
            const int b = m >> 2, p = m & 3;
            const float4 av = *reinterpret_cast<const float4*>(g_attn + (size_t)b * 4);
            const float a[4] = {av.x, av.y, av.z, av.w};
            const int nkb = (j & 1) * 2;
#pragma unroll
            for (int nt2 = 0; nt2 < 2; nt2++)
#pragma unroll
                for (int b3 = 0; b3 < 2; b3++) {
                    const float* c = cAcc[mt][nt2 * 2 + b3];
                    float partial = a[nkb] * c[h * 2 + 0] + a[nkb + 1] * c[h * 2 + 1];
                    partial += __shfl_xor_sync(0xffffffffu, partial, 1);
                    if ((j & 1) == 0) {
                        const int o = (n0 + wn * 32 + nt2 * 16 + b3 * 8) / 4 + (j >> 1);
                        const float bc = a[0] * bias_s[o] + a[1] * bias_s[64 + o]
                                       + a[2] * bias_s[128 + o] + a[3] * bias_s[192 + o];
                        g_feat[(size_t)b * 256 + o * 4 + p] = partial + bc;
                    }
                }
        }
    }
}

// ---------------------------------------------------------------------------
// B-spline bases, grid matches the reference knots bit-exactly.
// ---------------------------------------------------------------------------
__device__ __forceinline__ void bspline8(float t, float* __restrict__ o8)
{
    float g[12];
#pragma unroll
    for (int j = 0; j < 12; j++)
        g[j] = __fadd_rn(__fmul_rn((float)(j - 3), 0.4f), -1.0f);
    float b[11];
#pragma unroll
    for (int j = 0; j < 11; j++)
        b[j] = (t >= g[j] && t < g[j + 1]) ? 1.0f : 0.0f;
#pragma unroll
    for (int k = 1; k <= 3; k++) {
#pragma unroll
        for (int j = 0; j < 10; j++) {
            if (j < 11 - k) {
                float left  = (t - g[j])         * (1.0f / (g[j + k] - g[j]));
                float right = (g[j + k + 1] - t) * (1.0f / (g[j + k + 1] - g[j + 1]));
                b[j] = left * b[j] + right * b[j + 1];
            }
        }
    }
#pragma unroll
    for (int j = 0; j < 8; j++) o8[j] = b[j];
}

// ---------------------------------------------------------------------------
// KANLinear: KBT=64 samples/block, i-chunk 16, thread tile 4 samples x 4 outputs.
// ---------------------------------------------------------------------------
#define KAN_SMEM_FLOATS (KBT*256*2 + KIC*8*64 + KIC*64 + KBT*KIC*8)
#define KAN_SMEM_BYTES  (KAN_SMEM_FLOATS * 4)   // 200704

__global__ __launch_bounds__(256) void kan_kernel(
    const float* __restrict__ base_w,
    const float* __restrict__ spline_w,
    const float* __restrict__ scaler,
    float* __restrict__ out)
{
    extern __shared__ __align__(16) float sm[];
    float* feat = sm;                     // [64][256]
    float* sil  = feat + KBT * 256;       // [64][256]
    float* wsp  = sil  + KBT * 256;       // [i(16)][g(8)][o(64)]
    float* wb   = wsp  + KIC * 8 * 64;    // [i(16)][o(64)]
    float* bas  = wb   + KIC * 64;        // [s(64)][i(16)][g(8)]

    const int tid = threadIdx.x;
    const int b0  = blockIdx.x * KBT;

    {
        const float4* src = reinterpret_cast<const float4*>(g_feat + (size_t)b0 * 256);
#pragma unroll 4
        for (int r = 0; r < 16; r++) {
            int idx4 = tid + r * 256;
            float4 v = src[idx4];
            *reinterpret_cast<float4*>(&feat[idx4 * 4]) = v;
            float4 s;
            s.x = v.x / (1.f + expf(-v.x));
            s.y = v.y / (1.f + expf(-v.y));
            s.z = v.z / (1.f + expf(-v.z));
            s.w = v.w / (1.f + expf(-v.w));
            *reinterpret_cast<float4*>(&sil[idx4 * 4]) = s;
        }
    }

    const int og = tid & 15;
    const int sg = tid >> 4;
    float acc[4][4];
#pragma unroll
    for (int ss = 0; ss < 4; ss++)
#pragma unroll
        for (int r = 0; r < 4; r++) acc[ss][r] = 0.f;

    for (int ic = 0; ic < 16; ic++) {
        const int i0 = ic * KIC;
        __syncthreads();

#pragma unroll
        for (int r = 0; r < 8; r++) {
            int l4 = tid + r * 256;
            int o  = l4 & 63;
            int ig = l4 >> 6;
            int i  = ig >> 1;
            int gh = ig & 1;
            float4 v = reinterpret_cast<const float4*>(spline_w)[((size_t)o * 256 + i0 + i) * 2 + gh];
            float sc = scaler[(size_t)o * 256 + i0 + i];
            int gb = gh * 4;
            wsp[(i * 8 + gb + 0) * 64 + o] = v.x * sc;
            wsp[(i * 8 + gb + 1) * 64 + o] = v.y * sc;
            wsp[(i * 8 + gb + 2) * 64 + o] = v.z * sc;
            wsp[(i * 8 + gb + 3) * 64 + o] = v.w * sc;
        }
#pragma unroll
        for (int r = 0; r < 4; r++) {
            int l = tid + r * 256;
            int o = l & 63;
            int i = l >> 6;
            wb[i * 64 + o] = base_w[(size_t)o * 256 + i0 + i];
        }
#pragma unroll
        for (int r = 0; r < 4; r++) {
            int task = tid + r * 256;
            int s = task >> 4;
            int i = task & 15;
            float bb8[8];
            bspline8(feat[s * 256 + i0 + i], bb8);
            float4* dst = reinterpret_cast<float4*>(&bas[(s * KIC + i) * 8]);
            dst[0] = make_float4(bb8[0], bb8[1], bb8[2], bb8[3]);
            dst[1] = make_float4(bb8[4], bb8[5], bb8[6], bb8[7]);
        }
        __syncthreads();

        for (int i = 0; i < KIC; i++) {
            float4 wbv = *reinterpret_cast<const float4*>(&wb[i * 64 + og * 4]);
            float wvp[32];
#pragma unroll
            for (int g = 0; g < 8; g++)
                *reinterpret_cast<float4*>(&wvp[g * 4]) =
                    *reinterpret_cast<const float4*>(&wsp[(i * 8 + g) * 64 + og * 4]);
#pragma unroll
            for (int ss = 0; ss < 4; ss++) {
                const int s = sg * 4 + ss;
                const float sv = sil[s * 256 + i0 + i];
                const float4* bp = reinterpret_cast<const float4*>(&bas[(s * KIC + i) * 8]);
                float4 bA = bp[0], bB = bp[1];
                float bv[8] = {bA.x, bA.y, bA.z, bA.w, bB.x, bB.y, bB.z, bB.w};
                acc[ss][0] = fmaf(sv, wbv.x, acc[ss][0]);
                acc[ss][1] = fmaf(sv, wbv.y, acc[ss][1]);
                acc[ss][2] = fmaf(sv, wbv.z, acc[ss][2]);
                acc[ss][3] = fmaf(sv, wbv.w, acc[ss][3]);
#pragma unroll
                for (int g = 0; g < 8; g++) {
                    acc[ss][0] = fmaf(bv[g], wvp[g * 4 + 0], acc[ss][0]);
                    acc[ss][1] = fmaf(bv[g], wvp[g * 4 + 1], acc[ss][1]);
                    acc[ss][2] = fmaf(bv[g], wvp[g * 4 + 2], acc[ss][2]);
                    acc[ss][3] = fmaf(bv[g], wvp[g * 4 + 3], acc[ss][3]);
                }
            }
        }
    }

#pragma unroll
    for (int ss = 0; ss < 4; ss++) {
        const int b = b0 + sg * 4 + ss;
        *reinterpret_cast<float4*>(&out[(size_t)b * 64 + og * 4]) =
            make_float4(acc[ss][0], acc[ss][1], acc[ss][2], acc[ss][3]);
    }
}

// ---------------------------------------------------------------------------
// Launch
// ---------------------------------------------------------------------------
extern "C" void kernel_launch(void* const* d_in, const int* in_sizes, int n_in,
                              void* d_out, int out_size)
{
    const float* x    = (const float*)d_in[0];
    const float* w    = (const float*)d_in[1];
    const float* bias = (const float*)d_in[2];
    const float* fc1w = (const float*)d_in[3];
    const float* fc1b = (const float*)d_in[4];
    const float* fc2w = (const float*)d_in[5];
    const float* fc2b = (const float*)d_in[6];
    const float* kbw  = (const float*)d_in[7];
    const float* ksw  = (const float*)d_in[8];
    const float* kss  = (const float*)d_in[9];
    float* out = (float*)d_out;

    cudaFuncSetAttribute(gemm_kernel, cudaFuncAttributeMaxDynamicSharedMemorySize, GEMM_SMEM);
    cudaFuncSetAttribute(kan_kernel,  cudaFuncAttributeMaxDynamicSharedMemorySize, KAN_SMEM_BYTES);

    prep_x_kernel<<<BATCH, 256>>>(x);
    prep_w_kernel<<<NDIM, 256>>>(w);
    attn_kernel<<<BATCH / 16, 256>>>(fc1w, fc1b, fc2w, fc2b);
    gemm_kernel<<<dim3(NDIM / NT, MROWS / MT), 256, GEMM_SMEM>>>(bias);
    kan_kernel<<<BATCH / KBT, 256, KAN_SMEM_BYTES>>>(kbw, ksw, kss, out);
}

// round 10
// speedup vs baseline: 2.8765x; 1.0716x over previous
#include <cuda_runtime.h>
#include <cuda_bf16.h>
#include <math.h>
#include <stdint.h>

#define BATCH 8192
#define CIN   256
#define NK    4
#define COUT  64
#define KD    2304            // exact im2col K = 9 ij * 256 c (k = ij*256 + c)
#define MROWS (BATCH * 4)     // m = b*4 + p
#define NDIM  256             // n = o*4 + nk

// GEMM tiling
#define MT 128
#define NT 64
#define KC 64
#define NCHUNK (KD / KC)      // 36

// KAN tiling
#define KBT 32
#define KIC 8

// ---------------------------------------------------------------------------
// Static device scratch
// ---------------------------------------------------------------------------
__device__ __nv_bfloat16 g_Xth[(size_t)BATCH * 16 * 256];   // [b][q][c] hi
__device__ __nv_bfloat16 g_Xtl[(size_t)BATCH * 16 * 256];   // [b][q][c] lo
__device__ __nv_bfloat16 g_W2h[(size_t)NDIM * KD];
__device__ __nv_bfloat16 g_W2l[(size_t)NDIM * KD];
__device__ float g_feat[(size_t)BATCH * 256];
__device__ float g_pooled[(size_t)BATCH * CIN];
__device__ float g_attn[(size_t)BATCH * NK];

// ---------------------------------------------------------------------------
// PTX helpers
// ---------------------------------------------------------------------------
__device__ __forceinline__ unsigned smem_u32(const void* p) {
    unsigned a;
    asm("{ .reg .u64 t; cvta.to.shared.u64 t, %1; cvt.u32.u64 %0, t; }" : "=r"(a) : "l"(p));
    return a;
}
__device__ __forceinline__ void cp_async16(unsigned saddr, const void* g) {
    asm volatile("cp.async.cg.shared.global [%0], [%1], 16;" :: "r"(saddr), "l"(g));
}
#define CP_COMMIT() asm volatile("cp.async.commit_group;" ::: "memory")
#define CP_WAIT1()  asm volatile("cp.async.wait_group 1;" ::: "memory")

#define LDSM_X4(r0, r1, r2, r3, addr) \
    asm volatile("ldmatrix.sync.aligned.m8n8.x4.shared.b16 {%0,%1,%2,%3}, [%4];" \
                 : "=r"(r0), "=r"(r1), "=r"(r2), "=r"(r3) : "r"(addr))

#define MMA16816(c, a, b0, b1) \
    asm volatile("mma.sync.aligned.m16n8k16.row.col.f32.bf16.bf16.f32 " \
                 "{%0,%1,%2,%3}, {%4,%5,%6,%7}, {%8,%9}, {%0,%1,%2,%3};" \
                 : "+f"((c)[0]), "+f"((c)[1]), "+f"((c)[2]), "+f"((c)[3]) \
                 : "r"((a)[0]), "r"((a)[1]), "r"((a)[2]), "r"((a)[3]), \
                   "r"(b0), "r"(b1))

#define SWZ(o) ((o) ^ (((o) >> 3) & 0x70))

// ---------------------------------------------------------------------------
// Prep 1: x fp32 -> xT[b][q][c] hi/lo bf16 (compact, no im2col expansion)
//         + fused GAP. Coalesced flush via smem transpose.
// ---------------------------------------------------------------------------
__global__ __launch_bounds__(256) void prep_x_kernel(const float* __restrict__ x)
{
    __shared__ __align__(16) __nv_bfloat16 sh[16 * 256];
    __shared__ __align__(16) __nv_bfloat16 sl[16 * 256];
    const int b = blockIdx.x, c = threadIdx.x;

    const float4* src = reinterpret_cast<const float4*>(x + ((size_t)b * CIN + c) * 16);
    float4 v[4];
#pragma unroll
    for (int i = 0; i < 4; i++) v[i] = src[i];
    const float* f = reinterpret_cast<const float*>(v);

    float sum = 0.f;
#pragma unroll
    for (int e = 0; e < 16; e++) {
        float fv = f[e];
        sum += fv;
        __nv_bfloat16 h = __float2bfloat16(fv);
        sh[e * 256 + c] = h;
        sl[e * 256 + c] = __float2bfloat16(fv - __bfloat162float(h));
    }
    g_pooled[(size_t)b * CIN + c] = sum * (1.f / 16.f);
    __syncthreads();

    // flush 16*256 bf16 = 512 uint4 per array
    const uint4* s4h = reinterpret_cast<const uint4*>(sh);
    const uint4* s4l = reinterpret_cast<const uint4*>(sl);
    uint4* dh = reinterpret_cast<uint4*>(g_Xth + (size_t)b * 16 * 256);
    uint4* dl = reinterpret_cast<uint4*>(g_Xtl + (size_t)b * 16 * 256);
    dh[c]       = s4h[c];
    dh[c + 256] = s4h[c + 256];
    dl[c]       = s4l[c];
    dl[c + 256] = s4l[c + 256];
}

// ---------------------------------------------------------------------------
// Prep 2: weights -> W2[n][k], n = o*4 + nk, k = ij*256 + c, hi/lo bf16.
// ---------------------------------------------------------------------------
__global__ __launch_bounds__(256) void prep_w_kernel(const float* __restrict__ w)
{
    const int n = blockIdx.x, c = threadIdx.x;
    const int o = n >> 2, nk = n & 3;
    const float* wr = w + ((size_t)(nk * COUT + o) * CIN + c) * 9;
#pragma unroll
    for (int ij = 0; ij < 9; ij++) {
        float val = wr[ij];
        __nv_bfloat16 h = __float2bfloat16(val);
        __nv_bfloat16 l = __float2bfloat16(val - __bfloat162float(h));
        g_W2h[(size_t)n * KD + ij * 256 + c] = h;
        g_W2l[(size_t)n * KD + ij * 256 + c] = l;
    }
}

// ---------------------------------------------------------------------------
// Attention: 4 samples per block, fully parallel (no serial sample loop).
// ---------------------------------------------------------------------------
__global__ __launch_bounds__(256) void attn_kernel(
    const float* __restrict__ fc1w, const float* __restrict__ fc1b,
    const float* __restrict__ fc2w, const float* __restrict__ fc2b)
{
    __shared__ float ps[4][256];
    __shared__ float hid[4][64];
    __shared__ float logit[4][4];

    const int tid = threadIdx.x;
    const int g = tid >> 6, t = tid & 63;
    const int b_base = blockIdx.x * 4;

    for (int idx = tid; idx < 1024; idx += 256)
        reinterpret_cast<float*>(ps)[idx] = g_pooled[(size_t)b_base * 256 + idx];
    __syncthreads();

    {   // fc1: thread (g, h=t)
        const float4* wr = reinterpret_cast<const float4*>(fc1w + (size_t)t * 256);
        const float4* pr = reinterpret_cast<const float4*>(ps[g]);
        float sum = 0.f;
#pragma unroll
        for (int q = 0; q < 64; q++) {
            float4 a = wr[q]; float4 bb = pr[q];
            sum = fmaf(a.x, bb.x, sum); sum = fmaf(a.y, bb.y, sum);
            sum = fmaf(a.z, bb.z, sum); sum = fmaf(a.w, bb.w, sum);
        }
        hid[g][t] = fmaxf(sum + fc1b[t], 0.f);
    }
    __syncthreads();

    if (t < 4) {
        float sm = 0.f;
#pragma unroll
        for (int k2 = 0; k2 < 64; k2++) sm = fmaf(hid[g][k2], fc2w[t * 64 + k2], sm);
        logit[g][t] = (sm + fc2b[t]) * (1.0f / 34.0f);
    }
    __syncthreads();

    if (t == 0) {
        const int b = b_base + g;
        float l0 = logit[g][0], l1 = logit[g][1], l2 = logit[g][2], l3 = logit[g][3];
        float m  = fmaxf(fmaxf(l0, l1), fmaxf(l2, l3));
        float e0 = expf(l0 - m), e1 = expf(l1 - m), e2 = expf(l2 - m), e3 = expf(l3 - m);
        float inv = 1.f / (e0 + e1 + e2 + e3);
        g_attn[(size_t)b * 4 + 0] = e0 * inv;
        g_attn[(size_t)b * 4 + 1] = e1 * inv;
        g_attn[(size_t)b * 4 + 2] = e2 * inv;
        g_attn[(size_t)b * 4 + 3] = e3 * inv;
    }
}

// ---------------------------------------------------------------------------
// GEMM C[32768, 256] = X2 · W2^T (bf16 hi/lo 3-pass, fp32 reg accum).
// CTA 128x64, 8 warps (4m x 2n), 2-stage, 2 CTAs/SM.
// A is loaded via IMPLICIT im2col from compact xT[b][q][c]:
//   chunk ch -> ij = ch>>2, cb = (ch&3)*64; row m=(b,p) reads xT[b][q(p,ij)][cb..]
// ---------------------------------------------------------------------------
#define ST_AH 0
#define ST_AL 16384
#define ST_BH 32768
#define ST_BL 40960
#define ST_SZ 49152
#define GEMM_SMEM (2 * ST_SZ)   // 98304

__global__ __launch_bounds__(256, 2) void gemm_kernel(const float* __restrict__ bias)
{
    extern __shared__ __align__(1024) char smem[];
    __shared__ float bias_s[256];

    const unsigned sb = smem_u32(smem);
    const int tid = threadIdx.x;
    const int wid = tid >> 5, lane = tid & 31;
    const int wm = wid >> 1, wn = wid & 1;
    const int n0 = blockIdx.x * NT;
    const int m0 = blockIdx.y * MT;

    bias_s[tid] = bias[tid];

    const char* Xh = (const char*)g_Xth;
    const char* Xl = (const char*)g_Xtl;
    const char* Wh = (const char*)g_W2h;
    const char* Wl = (const char*)g_W2l;

    auto load_chunk = [&](int ch, int stg) {
        const unsigned st = sb + stg * ST_SZ;
        const int ij = ch >> 2;
        const int cb = (ch & 3) * 64;
        const int di = ij / 3, dj = ij - di * 3;
        const size_t kb = (size_t)ch * 128;        // B byte offset (k = ij*256+c)
#pragma unroll
        for (int i = 0; i < 4; i++) {
            int s = tid + i * 256;
            int row = s >> 3, seg = s & 7;
            unsigned so = SWZ(row * 128 + seg * 16);
            const int m = m0 + row;
            const int b = m >> 2, p = m & 3;
            const int q = ((p >> 1) + di) * 4 + (p & 1) + dj;
            size_t ga = ((size_t)b * 16 + q) * 512 + cb * 2 + seg * 16;
            cp_async16(st + ST_AH + so, Xh + ga);
            cp_async16(st + ST_AL + so, Xl + ga);
        }
#pragma unroll
        for (int i = 0; i < 2; i++) {
            int s = tid + i * 256;
            int row = s >> 3, seg = s & 7;
            unsigned so = SWZ(row * 128 + seg * 16);
            size_t gb = (size_t)(n0 + row) * (KD * 2) + kb + seg * 16;
            cp_async16(st + ST_BH + so, Wh + gb);
            cp_async16(st + ST_BL + so, Wl + gb);
        }
    };

    float cAcc[2][4][4];
#pragma unroll
    for (int m = 0; m < 2; m++)
#pragma unroll
        for (int n = 0; n < 4; n++)
#pragma unroll
            for (int r = 0; r < 4; r++) cAcc[m][n][r] = 0.f;

    load_chunk(0, 0); CP_COMMIT();
    load_chunk(1, 1); CP_COMMIT();

    const int arow = lane & 15;
    const int aseg = (lane >> 4) << 4;

    for (int ch = 0; ch < NCHUNK; ch++) {
        const int stg = ch & 1;
        const unsigned st = sb + stg * ST_SZ;
        CP_WAIT1();
        __syncthreads();

#pragma unroll
        for (int ks = 0; ks < 4; ks++) {
            const int kb2 = ks * 32 + aseg;
            unsigned ah[2][4], al[2][4], bh[2][4], bl[2][4];
#pragma unroll
            for (int mt = 0; mt < 2; mt++) {
                int r = wm * 32 + mt * 16 + arow;
                unsigned so = SWZ(r * 128 + kb2);
                LDSM_X4(ah[mt][0], ah[mt][1], ah[mt][2], ah[mt][3], st + ST_AH + so);
                LDSM_X4(al[mt][0], al[mt][1], al[mt][2], al[mt][3], st + ST_AL + so);
            }
#pragma unroll
            for (int nt2 = 0; nt2 < 2; nt2++) {
                int r = wn * 32 + nt2 * 16 + arow;
                unsigned so = SWZ(r * 128 + kb2);
                LDSM_X4(bh[nt2][0], bh[nt2][1], bh[nt2][2], bh[nt2][3], st + ST_BH + so);
                LDSM_X4(bl[nt2][0], bl[nt2][1], bl[nt2][2], bl[nt2][3], st + ST_BL + so);
            }
#pragma unroll
            for (int mt = 0; mt < 2; mt++)
#pragma unroll
                for (int nt2 = 0; nt2 < 2; nt2++)
#pragma unroll
                    for (int b3 = 0; b3 < 2; b3++)
                        MMA16816(cAcc[mt][nt2 * 2 + b3], ah[mt], bh[nt2][b3], bh[nt2][b3 + 2]);
#pragma unroll
            for (int mt = 0; mt < 2; mt++)
#pragma unroll
                for (int nt2 = 0; nt2 < 2; nt2++)
#pragma unroll
                    for (int b3 = 0; b3 < 2; b3++)
                        MMA16816(cAcc[mt][nt2 * 2 + b3], al[mt], bh[nt2][b3], bh[nt2][b3 + 2]);
#pragma unroll
            for (int mt = 0; mt < 2; mt++)
#pragma unroll
                for (int nt2 = 0; nt2 < 2; nt2++)
#pragma unroll
                    for (int b3 = 0; b3 < 2; b3++)
                        MMA16816(cAcc[mt][nt2 * 2 + b3], ah[mt], bl[nt2][b3], bl[nt2][b3 + 2]);
        }

        __syncthreads();
        if (ch + 2 < NCHUNK) load_chunk(ch + 2, stg);
        CP_COMMIT();
    }

    // ---- epilogue: combine nk via lane-pair shfl, add bias, write g_feat ----
    const int j = lane & 3;
    const int rbase = wm * 32 + (lane >> 2);
#pragma unroll
    for (int mt = 0; mt < 2; mt++) {
#pragma unroll
        for (int h = 0; h < 2; h++) {
            const int m = m0 + rbase + mt * 16 + h * 8;
            const int b = m >> 2, p = m & 3;
            const float4 av = *reinterpret_cast<const float4*>(g_attn + (size_t)b * 4);
            const float a[4] = {av.x, av.y, av.z, av.w};
            const int nkb = (j & 1) * 2;
#pragma unroll
            for (int nt2 = 0; nt2 < 2; nt2++)
#pragma unroll
                for (int b3 = 0; b3 < 2; b3++) {
                    const float* c = cAcc[mt][nt2 * 2 + b3];
                    float partial = a[nkb] * c[h * 2 + 0] + a[nkb + 1] * c[h * 2 + 1];
                    partial += __shfl_xor_sync(0xffffffffu, partial, 1);
                    if ((j & 1) == 0) {
                        const int o = (n0 + wn * 32 + nt2 * 16 + b3 * 8) / 4 + (j >> 1);
                        const float bc = a[0] * bias_s[o] + a[1] * bias_s[64 + o]
                                       + a[2] * bias_s[128 + o] + a[3] * bias_s[192 + o];
                        g_feat[(size_t)b * 256 + o * 4 + p] = partial + bc;
                    }
                }
        }
    }
}

// ---------------------------------------------------------------------------
// B-spline bases, grid matches the reference knots bit-exactly.
// ---------------------------------------------------------------------------
__device__ __forceinline__ void bspline8(float t, float* __restrict__ o8)
{
    float g[12];
#pragma unroll
    for (int j = 0; j < 12; j++)
        g[j] = __fadd_rn(__fmul_rn((float)(j - 3), 0.4f), -1.0f);
    float b[11];
#pragma unroll
    for (int j = 0; j < 11; j++)
        b[j] = (t >= g[j] && t < g[j + 1]) ? 1.0f : 0.0f;
#pragma unroll
    for (int k = 1; k <= 3; k++) {
#pragma unroll
        for (int j = 0; j < 10; j++) {
            if (j < 11 - k) {
                float left  = (t - g[j])         * (1.0f / (g[j + k] - g[j]));
                float right = (g[j + k + 1] - t) * (1.0f / (g[j + k + 1] - g[j + 1]));
                b[j] = left * b[j] + right * b[j + 1];
            }
        }
    }
#pragma unroll
    for (int j = 0; j < 8; j++) o8[j] = b[j];
}

// ---------------------------------------------------------------------------
// KANLinear: KBT=32, KIC=8 -> 90 KB smem -> 2 blocks/SM.
// Thread tile: 2 samples x 4 outputs (og = tid&15, sg = tid>>4).
// ---------------------------------------------------------------------------
#define KAN_SMEM_FLOATS (KBT*256*2 + KIC*8*64 + KIC*64 + KBT*KIC*8)
#define KAN_SMEM_BYTES  (KAN_SMEM_FLOATS * 4)   // 92160

__global__ __launch_bounds__(256, 2) void kan_kernel(
    const float* __restrict__ base_w,
    const float* __restrict__ spline_w,
    const float* __restrict__ scaler,
    float* __restrict__ out)
{
    extern __shared__ __align__(16) float sm[];
    float* feat = sm;                     // [32][256]
    float* sil  = feat + KBT * 256;       // [32][256]
    float* wsp  = sil  + KBT * 256;       // [i(8)][g(8)][o(64)]
    float* wb   = wsp  + KIC * 8 * 64;    // [i(8)][o(64)]
    float* bas  = wb   + KIC * 64;        // [s(32)][i(8)][g(8)]

    const int tid = threadIdx.x;
    const int b0  = blockIdx.x * KBT;

    {   // load feat, compute silu
        const float4* src = reinterpret_cast<const float4*>(g_feat + (size_t)b0 * 256);
#pragma unroll
        for (int r = 0; r < 8; r++) {
            int idx4 = tid + r * 256;
            float4 v = src[idx4];
            *reinterpret_cast<float4*>(&feat[idx4 * 4]) = v;
            float4 s;
            s.x = v.x / (1.f + expf(-v.x));
            s.y = v.y / (1.f + expf(-v.y));
            s.z = v.z / (1.f + expf(-v.z));
            s.w = v.w / (1.f + expf(-v.w));
            *reinterpret_cast<float4*>(&sil[idx4 * 4]) = s;
        }
    }

    const int og = tid & 15;
    const int sg = tid >> 4;
    float acc[2][4] = {{0.f, 0.f, 0.f, 0.f}, {0.f, 0.f, 0.f, 0.f}};

    for (int ic = 0; ic < 32; ic++) {
        const int i0 = ic * KIC;
        __syncthreads();

        // spline weights (pre-scaled), [i][g][o]: 4096 floats
#pragma unroll
        for (int r = 0; r < 4; r++) {
            int l4 = tid + r * 256;
            int o  = l4 & 63;
            int ig = l4 >> 6;        // 0..15
            int i  = ig >> 1;
            int gh = ig & 1;
            float4 v = reinterpret_cast<const float4*>(spline_w)[((size_t)o * 256 + i0 + i) * 2 + gh];
            float sc = scaler[(size_t)o * 256 + i0 + i];
            int gb = gh * 4;
            wsp[(i * 8 + gb + 0) * 64 + o] = v.x * sc;
            wsp[(i * 8 + gb + 1) * 64 + o] = v.y * sc;
            wsp[(i * 8 + gb + 2) * 64 + o] = v.z * sc;
            wsp[(i * 8 + gb + 3) * 64 + o] = v.w * sc;
        }
        // base weights chunk [i][o]: 512 floats
#pragma unroll
        for (int r = 0; r < 2; r++) {
            int l = tid + r * 256;
            int o = l & 63;
            int i = l >> 6;
            wb[i * 64 + o] = base_w[(size_t)o * 256 + i0 + i];
        }
        // bases chunk: 32 s x 8 i = 256 evals, one per thread
        {
            int s = tid >> 3, i = tid & 7;
            float bb8[8];
            bspline8(feat[s * 256 + i0 + i], bb8);
            float4* dst = reinterpret_cast<float4*>(&bas[(s * KIC + i) * 8]);
            dst[0] = make_float4(bb8[0], bb8[1], bb8[2], bb8[3]);
            dst[1] = make_float4(bb8[4], bb8[5], bb8[6], bb8[7]);
        }
        __syncthreads();

        for (int i = 0; i < KIC; i++) {
            float4 wbv = *reinterpret_cast<const float4*>(&wb[i * 64 + og * 4]);
            float wvp[32];
#pragma unroll
            for (int g = 0; g < 8; g++)
                *reinterpret_cast<float4*>(&wvp[g * 4]) =
                    *reinterpret_cast<const float4*>(&wsp[(i * 8 + g) * 64 + og * 4]);
#pragma unroll
            for (int ss = 0; ss < 2; ss++) {
                const int s = sg * 2 + ss;
                const float sv = sil[s * 256 + i0 + i];
                const float4* bp = reinterpret_cast<const float4*>(&bas[(s * KIC + i) * 8]);
                float4 bA = bp[0], bB = bp[1];
                float bv[8] = {bA.x, bA.y, bA.z, bA.w, bB.x, bB.y, bB.z, bB.w};
                acc[ss][0] = fmaf(sv, wbv.x, acc[ss][0]);
                acc[ss][1] = fmaf(sv, wbv.y, acc[ss][1]);
                acc[ss][2] = fmaf(sv, wbv.z, acc[ss][2]);
                acc[ss][3] = fmaf(sv, wbv.w, acc[ss][3]);
#pragma unroll
                for (int g = 0; g < 8; g++) {
                    acc[ss][0] = fmaf(bv[g], wvp[g * 4 + 0], acc[ss][0]);
                    acc[ss][1] = fmaf(bv[g], wvp[g * 4 + 1], acc[ss][1]);
                    acc[ss][2] = fmaf(bv[g], wvp[g * 4 + 2], acc[ss][2]);
                    acc[ss][3] = fmaf(bv[g], wvp[g * 4 + 3], acc[ss][3]);
                }
            }
        }
    }

#pragma unroll
    for (int ss = 0; ss < 2; ss++) {
        const int b = b0 + sg * 2 + ss;
        *reinterpret_cast<float4*>(&out[(size_t)b * 64 + og * 4]) =
            make_float4(acc[ss][0], acc[ss][1], acc[ss][2], acc[ss][3]);
    }
}

// ---------------------------------------------------------------------------
// Launch
// ---------------------------------------------------------------------------
extern "C" void kernel_launch(void* const* d_in, const int* in_sizes, int n_in,
                              void* d_out, int out_size)
{
    const float* x    = (const float*)d_in[0];
    const float* w    = (const float*)d_in[1];
    const float* bias = (const float*)d_in[2];
    const float* fc1w = (const float*)d_in[3];
    const float* fc1b = (const float*)d_in[4];
    const float* fc2w = (const float*)d_in[5];
    const float* fc2b = (const float*)d_in[6];
    const float* kbw  = (const float*)d_in[7];
    const float* ksw  = (const float*)d_in[8];
    const float* kss  = (const float*)d_in[9];
    float* out = (float*)d_out;

    cudaFuncSetAttribute(gemm_kernel, cudaFuncAttributeMaxDynamicSharedMemorySize, GEMM_SMEM);
    cudaFuncSetAttribute(kan_kernel,  cudaFuncAttributeMaxDynamicSharedMemorySize, KAN_SMEM_BYTES);

    prep_x_kernel<<<BATCH, 256>>>(x);
    prep_w_kernel<<<NDIM, 256>>>(w);
    attn_kernel<<<BATCH / 4, 256>>>(fc1w, fc1b, fc2w, fc2b);
    gemm_kernel<<<dim3(NDIM / NT, MROWS / MT), 256, GEMM_SMEM>>>(bias);
    kan_kernel<<<BATCH / KBT, 256, KAN_SMEM_BYTES>>>(kbw, ksw, kss, out);
}

// round 11
// speedup vs baseline: 2.9494x; 1.0254x over previous
#include <cuda_runtime.h>
#include <cuda_bf16.h>
#include <math.h>
#include <stdint.h>

#define BATCH 8192
#define CIN   256
#define NK    4
#define COUT  64
#define KD    2304            // exact im2col K = 9 ij * 256 c (k = ij*256 + c)
#define MROWS (BATCH * 4)     // m = b*4 + p
#define NDIM  256             // n = o*4 + nk

// GEMM tiling
#define MT 64
#define NT 64
#define KC 64
#define NCHUNK (KD / KC)      // 36
#define GTHREADS 128

// KAN tiling
#define KBT 32
#define KIC 8

// ---------------------------------------------------------------------------
// Static device scratch
// ---------------------------------------------------------------------------
__device__ __nv_bfloat16 g_Xth[(size_t)BATCH * 16 * 256];   // [b][q][c] hi
__device__ __nv_bfloat16 g_Xtl[(size_t)BATCH * 16 * 256];   // [b][q][c] lo
__device__ __nv_bfloat16 g_W2h[(size_t)NDIM * KD];
__device__ __nv_bfloat16 g_W2l[(size_t)NDIM * KD];
__device__ float g_feat[(size_t)BATCH * 256];
__device__ float g_pooled[(size_t)BATCH * CIN];
__device__ float g_attn[(size_t)BATCH * NK];

// ---------------------------------------------------------------------------
// PTX helpers
// ---------------------------------------------------------------------------
__device__ __forceinline__ unsigned smem_u32(const void* p) {
    unsigned a;
    asm("{ .reg .u64 t; cvta.to.shared.u64 t, %1; cvt.u32.u64 %0, t; }" : "=r"(a) : "l"(p));
    return a;
}
__device__ __forceinline__ void cp_async16(unsigned saddr, const void* g) {
    asm volatile("cp.async.cg.shared.global [%0], [%1], 16;" :: "r"(saddr), "l"(g));
}
#define CP_COMMIT() asm volatile("cp.async.commit_group;" ::: "memory")
#define CP_WAIT1()  asm volatile("cp.async.wait_group 1;" ::: "memory")

#define LDSM_X4(r0, r1, r2, r3, addr) \
    asm volatile("ldmatrix.sync.aligned.m8n8.x4.shared.b16 {%0,%1,%2,%3}, [%4];" \
                 : "=r"(r0), "=r"(r1), "=r"(r2), "=r"(r3) : "r"(addr))

#define MMA16816(c, a, b0, b1) \
    asm volatile("mma.sync.aligned.m16n8k16.row.col.f32.bf16.bf16.f32 " \
                 "{%0,%1,%2,%3}, {%4,%5,%6,%7}, {%8,%9}, {%0,%1,%2,%3};" \
                 : "+f"((c)[0]), "+f"((c)[1]), "+f"((c)[2]), "+f"((c)[3]) \
                 : "r"((a)[0]), "r"((a)[1]), "r"((a)[2]), "r"((a)[3]), \
                   "r"(b0), "r"(b1))

#define SWZ(o) ((o) ^ (((o) >> 3) & 0x70))

// ---------------------------------------------------------------------------
// Prep 1: x fp32 -> xT[b][q][c] hi/lo bf16 + fused GAP.
// ---------------------------------------------------------------------------
__global__ __launch_bounds__(256) void prep_x_kernel(const float* __restrict__ x)
{
    __shared__ __align__(16) __nv_bfloat16 sh[16 * 256];
    __shared__ __align__(16) __nv_bfloat16 sl[16 * 256];
    const int b = blockIdx.x, c = threadIdx.x;

    const float4* src = reinterpret_cast<const float4*>(x + ((size_t)b * CIN + c) * 16);
    float4 v[4];
#pragma unroll
    for (int i = 0; i < 4; i++) v[i] = src[i];
    const float* f = reinterpret_cast<const float*>(v);

    float sum = 0.f;
#pragma unroll
    for (int e = 0; e < 16; e++) {
        float fv = f[e];
        sum += fv;
        __nv_bfloat16 h = __float2bfloat16(fv);
        sh[e * 256 + c] = h;
        sl[e * 256 + c] = __float2bfloat16(fv - __bfloat162float(h));
    }
    g_pooled[(size_t)b * CIN + c] = sum * (1.f / 16.f);
    __syncthreads();

    const uint4* s4h = reinterpret_cast<const uint4*>(sh);
    const uint4* s4l = reinterpret_cast<const uint4*>(sl);
    uint4* dh = reinterpret_cast<uint4*>(g_Xth + (size_t)b * 16 * 256);
    uint4* dl = reinterpret_cast<uint4*>(g_Xtl + (size_t)b * 16 * 256);
    dh[c]       = s4h[c];
    dh[c + 256] = s4h[c + 256];
    dl[c]       = s4l[c];
    dl[c + 256] = s4l[c + 256];
}

// ---------------------------------------------------------------------------
// Prep 2: weights -> W2[n][k], n = o*4 + nk, k = ij*256 + c, hi/lo bf16.
// ---------------------------------------------------------------------------
__global__ __launch_bounds__(256) void prep_w_kernel(const float* __restrict__ w)
{
    const int n = blockIdx.x, c = threadIdx.x;
    const int o = n >> 2, nk = n & 3;
    const float* wr = w + ((size_t)(nk * COUT + o) * CIN + c) * 9;
#pragma unroll
    for (int ij = 0; ij < 9; ij++) {
        float val = wr[ij];
        __nv_bfloat16 h = __float2bfloat16(val);
        __nv_bfloat16 l = __float2bfloat16(val - __bfloat162float(h));
        g_W2h[(size_t)n * KD + ij * 256 + c] = h;
        g_W2l[(size_t)n * KD + ij * 256 + c] = l;
    }
}

// ---------------------------------------------------------------------------
// Attention: 4 samples per block, fully parallel.
// ---------------------------------------------------------------------------
__global__ __launch_bounds__(256) void attn_kernel(
    const float* __restrict__ fc1w, const float* __restrict__ fc1b,
    const float* __restrict__ fc2w, const float* __restrict__ fc2b)
{
    __shared__ float ps[4][256];
    __shared__ float hid[4][64];
    __shared__ float logit[4][4];

    const int tid = threadIdx.x;
    const int g = tid >> 6, t = tid & 63;
    const int b_base = blockIdx.x * 4;

    for (int idx = tid; idx < 1024; idx += 256)
        reinterpret_cast<float*>(ps)[idx] = g_pooled[(size_t)b_base * 256 + idx];
    __syncthreads();

    {
        const float4* wr = reinterpret_cast<const float4*>(fc1w + (size_t)t * 256);
        const float4* pr = reinterpret_cast<const float4*>(ps[g]);
        float sum = 0.f;
#pragma unroll
        for (int q = 0; q < 64; q++) {
            float4 a = wr[q]; float4 bb = pr[q];
            sum = fmaf(a.x, bb.x, sum); sum = fmaf(a.y, bb.y, sum);
            sum = fmaf(a.z, bb.z, sum); sum = fmaf(a.w, bb.w, sum);
        }
        hid[g][t] = fmaxf(sum + fc1b[t], 0.f);
    }
    __syncthreads();

    if (t < 4) {
        float sm = 0.f;
#pragma unroll
        for (int k2 = 0; k2 < 64; k2++) sm = fmaf(hid[g][k2], fc2w[t * 64 + k2], sm);
        logit[g][t] = (sm + fc2b[t]) * (1.0f / 34.0f);
    }
    __syncthreads();

    if (t == 0) {
        const int b = b_base + g;
        float l0 = logit[g][0], l1 = logit[g][1], l2 = logit[g][2], l3 = logit[g][3];
        float m  = fmaxf(fmaxf(l0, l1), fmaxf(l2, l3));
        float e0 = expf(l0 - m), e1 = expf(l1 - m), e2 = expf(l2 - m), e3 = expf(l3 - m);
        float inv = 1.f / (e0 + e1 + e2 + e3);
        g_attn[(size_t)b * 4 + 0] = e0 * inv;
        g_attn[(size_t)b * 4 + 1] = e1 * inv;
        g_attn[(size_t)b * 4 + 2] = e2 * inv;
        g_attn[(size_t)b * 4 + 3] = e3 * inv;
    }
}

// ---------------------------------------------------------------------------
// GEMM C[32768, 256] = X2 · W2^T (bf16 hi/lo 3-pass, fp32 reg accum).
// CTA 64x64, 128 threads, 4 warps (2m x 2n), warp tile 32x32 (unchanged),
// 2-stage (64 KB) -> 3 CTAs/SM. Implicit im2col from compact xT.
// ---------------------------------------------------------------------------
#define ST_AH 0
#define ST_AL 8192
#define ST_BH 16384
#define ST_BL 24576
#define ST_SZ 32768
#define GEMM_SMEM (2 * ST_SZ)   // 65536

__global__ __launch_bounds__(GTHREADS, 3) void gemm_kernel(const float* __restrict__ bias)
{
    extern __shared__ __align__(1024) char smem[];
    __shared__ float bias_s[256];

    const unsigned sb = smem_u32(smem);
    const int tid = threadIdx.x;
    const int wid = tid >> 5, lane = tid & 31;
    const int wm = wid >> 1, wn = wid & 1;
    const int n0 = blockIdx.x * NT;
    const int m0 = blockIdx.y * MT;

    bias_s[tid] = bias[tid];
    bias_s[tid + 128] = bias[tid + 128];

    const char* Xh = (const char*)g_Xth;
    const char* Xl = (const char*)g_Xtl;
    const char* Wh = (const char*)g_W2h;
    const char* Wl = (const char*)g_W2l;

    auto load_chunk = [&](int ch, int stg) {
        const unsigned st = sb + stg * ST_SZ;
        const int ij = ch >> 2;
        const int cb = (ch & 3) * 64;
        const int di = ij / 3, dj = ij - di * 3;
        const size_t kb = (size_t)ch * 128;
#pragma unroll
        for (int i = 0; i < 4; i++) {
            int s = tid + i * GTHREADS;            // 512 A tasks
            int row = s >> 3, seg = s & 7;
            unsigned so = SWZ(row * 128 + seg * 16);
            const int m = m0 + row;
            const int b = m >> 2, p = m & 3;
            const int q = ((p >> 1) + di) * 4 + (p & 1) + dj;
            size_t ga = ((size_t)b * 16 + q) * 512 + cb * 2 + seg * 16;
            cp_async16(st + ST_AH + so, Xh + ga);
            cp_async16(st + ST_AL + so, Xl + ga);
        }
#pragma unroll
        for (int i = 0; i < 4; i++) {
            int s = tid + i * GTHREADS;            // 512 B tasks
            int row = s >> 3, seg = s & 7;
            unsigned so = SWZ(row * 128 + seg * 16);
            size_t gb = (size_t)(n0 + row) * (KD * 2) + kb + seg * 16;
            cp_async16(st + ST_BH + so, Wh + gb);
            cp_async16(st + ST_BL + so, Wl + gb);
        }
    };

    float cAcc[2][4][4];
#pragma unroll
    for (int m = 0; m < 2; m++)
#pragma unroll
        for (int n = 0; n < 4; n++)
#pragma unroll
            for (int r = 0; r < 4; r++) cAcc[m][n][r] = 0.f;

    load_chunk(0, 0); CP_COMMIT();
    load_chunk(1, 1); CP_COMMIT();

    const int arow = lane & 15;
    const int aseg = (lane >> 4) << 4;

    for (int ch = 0; ch < NCHUNK; ch++) {
        const int stg = ch & 1;
        const unsigned st = sb + stg * ST_SZ;
        CP_WAIT1();
        __syncthreads();

#pragma unroll
        for (int ks = 0; ks < 4; ks++) {
            const int kb2 = ks * 32 + aseg;
            unsigned ah[2][4], al[2][4], bh[2][4], bl[2][4];
#pragma unroll
            for (int mt = 0; mt < 2; mt++) {
                int r = wm * 32 + mt * 16 + arow;
                unsigned so = SWZ(r * 128 + kb2);
                LDSM_X4(ah[mt][0], ah[mt][1], ah[mt][2], ah[mt][3], st + ST_AH + so);
                LDSM_X4(al[mt][0], al[mt][1], al[mt][2], al[mt][3], st + ST_AL + so);
            }
#pragma unroll
            for (int nt2 = 0; nt2 < 2; nt2++) {
                int r = wn * 32 + nt2 * 16 + arow;
                unsigned so = SWZ(r * 128 + kb2);
                LDSM_X4(bh[nt2][0], bh[nt2][1], bh[nt2][2], bh[nt2][3], st + ST_BH + so);
                LDSM_X4(bl[nt2][0], bl[nt2][1], bl[nt2][2], bl[nt2][3], st + ST_BL + so);
            }
#pragma unroll
            for (int mt = 0; mt < 2; mt++)
#pragma unroll
                for (int nt2 = 0; nt2 < 2; nt2++)
#pragma unroll
                    for (int b3 = 0; b3 < 2; b3++)
                        MMA16816(cAcc[mt][nt2 * 2 + b3], ah[mt], bh[nt2][b3], bh[nt2][b3 + 2]);
#pragma unroll
            for (int mt = 0; mt < 2; mt++)
#pragma unroll
                for (int nt2 = 0; nt2 < 2; nt2++)
#pragma unroll
                    for (int b3 = 0; b3 < 2; b3++)
                        MMA16816(cAcc[mt][nt2 * 2 + b3], al[mt], bh[nt2][b3], bh[nt2][b3 + 2]);
#pragma unroll
            for (int mt = 0; mt < 2; mt++)
#pragma unroll
                for (int nt2 = 0; nt2 < 2; nt2++)
#pragma unroll
                    for (int b3 = 0; b3 < 2; b3++)
                        MMA16816(cAcc[mt][nt2 * 2 + b3], ah[mt], bl[nt2][b3], bl[nt2][b3 + 2]);
        }

        __syncthreads();
        if (ch + 2 < NCHUNK) load_chunk(ch + 2, stg);
        CP_COMMIT();
    }

    // ---- epilogue: combine nk via lane-pair shfl, add bias, write g_feat ----
    const int j = lane & 3;
    const int rbase = wm * 32 + (lane >> 2);
#pragma unroll
    for (int mt = 0; mt < 2; mt++) {
#pragma unroll
        for (int h = 0; h < 2; h++) {
            const int m = m0 + rbase + mt * 16 + h * 8;
            const int b = m >> 2, p = m & 3;
            const float4 av = *reinterpret_cast<const float4*>(g_attn + (size_t)b * 4);
            const float a[4] = {av.x, av.y, av.z, av.w};
            const int nkb = (j & 1) * 2;
#pragma unroll
            for (int nt2 = 0; nt2 < 2; nt2++)
#pragma unroll
                for (int b3 = 0; b3 < 2; b3++) {
                    const float* c = cAcc[mt][nt2 * 2 + b3];
                    float partial = a[nkb] * c[h * 2 + 0] + a[nkb + 1] * c[h * 2 + 1];
                    partial += __shfl_xor_sync(0xffffffffu, partial, 1);
                    if ((j & 1) == 0) {
                        const int o = (n0 + wn * 32 + nt2 * 16 + b3 * 8) / 4 + (j >> 1);
                        const float bc = a[0] * bias_s[o] + a[1] * bias_s[64 + o]
                                       + a[2] * bias_s[128 + o] + a[3] * bias_s[192 + o];
                        g_feat[(size_t)b * 256 + o * 4 + p] = partial + bc;
                    }
                }
        }
    }
}

// ---------------------------------------------------------------------------
// B-spline bases, grid matches the reference knots bit-exactly.
// ---------------------------------------------------------------------------
__device__ __forceinline__ void bspline8(float t, float* __restrict__ o8)
{
    float g[12];
#pragma unroll
    for (int j = 0; j < 12; j++)
        g[j] = __fadd_rn(__fmul_rn((float)(j - 3), 0.4f), -1.0f);
    float b[11];
#pragma unroll
    for (int j = 0; j < 11; j++)
        b[j] = (t >= g[j] && t < g[j + 1]) ? 1.0f : 0.0f;
#pragma unroll
    for (int k = 1; k <= 3; k++) {
#pragma unroll
        for (int j = 0; j < 10; j++) {
            if (j < 11 - k) {
                float left  = (t - g[j])         * (1.0f / (g[j + k] - g[j]));
                float right = (g[j + k + 1] - t) * (1.0f / (g[j + k + 1] - g[j + 1]));
                b[j] = left * b[j] + right * b[j + 1];
            }
        }
    }
#pragma unroll
    for (int j = 0; j < 8; j++) o8[j] = b[j];
}

// ---------------------------------------------------------------------------
// KANLinear: KBT=32, 128 threads, KIC=8, thread tile 4 samples x 4 outputs,
// 90 KB smem -> 2 blocks/SM.
// ---------------------------------------------------------------------------
#define KAN_SMEM_FLOATS (KBT*256*2 + KIC*8*64 + KIC*64 + KBT*KIC*8)
#define KAN_SMEM_BYTES  (KAN_SMEM_FLOATS * 4)   // 92160

__global__ __launch_bounds__(128, 2) void kan_kernel(
    const float* __restrict__ base_w,
    const float* __restrict__ spline_w,
    const float* __restrict__ scaler,
    float* __restrict__ out)
{
    extern __shared__ __align__(16) float sm[];
    float* feat = sm;                     // [32][256]
    float* sil  = feat + KBT * 256;       // [32][256]
    float* wsp  = sil  + KBT * 256;       // [i(8)][g(8)][o(64)]
    float* wb   = wsp  + KIC * 8 * 64;    // [i(8)][o(64)]
    float* bas  = wb   + KIC * 64;        // [s(32)][i(8)][g(8)]

    const int tid = threadIdx.x;
    const int b0  = blockIdx.x * KBT;

    {   // load feat, compute silu: 2048 float4 / 128 threads
        const float4* src = reinterpret_cast<const float4*>(g_feat + (size_t)b0 * 256);
#pragma unroll
        for (int r = 0; r < 16; r++) {
            int idx4 = tid + r * 128;
            float4 v = src[idx4];
            *reinterpret_cast<float4*>(&feat[idx4 * 4]) = v;
            float4 s;
            s.x = v.x / (1.f + expf(-v.x));
            s.y = v.y / (1.f + expf(-v.y));
            s.z = v.z / (1.f + expf(-v.z));
            s.w = v.w / (1.f + expf(-v.w));
            *reinterpret_cast<float4*>(&sil[idx4 * 4]) = s;
        }
    }

    const int og = tid & 15;      // outputs og*4..+3
    const int sg = tid >> 4;      // samples sg*4..+3  (8 groups x 4 = 32)
    float acc[4][4];
#pragma unroll
    for (int ss = 0; ss < 4; ss++)
#pragma unroll
        for (int r = 0; r < 4; r++) acc[ss][r] = 0.f;

    for (int ic = 0; ic < 32; ic++) {
        const int i0 = ic * KIC;
        __syncthreads();

        // spline weights (pre-scaled), [i][g][o]: 1024 float4 tasks / 128 thr
#pragma unroll
        for (int r = 0; r < 8; r++) {
            int l4 = tid + r * 128;
            int o  = l4 & 63;
            int ig = l4 >> 6;        // 0..15
            int i  = ig >> 1;
            int gh = ig & 1;
            float4 v = reinterpret_cast<const float4*>(spline_w)[((size_t)o * 256 + i0 + i) * 2 + gh];
            float sc = scaler[(size_t)o * 256 + i0 + i];
            int gb = gh * 4;
            wsp[(i * 8 + gb + 0) * 64 + o] = v.x * sc;
            wsp[(i * 8 + gb + 1) * 64 + o] = v.y * sc;
            wsp[(i * 8 + gb + 2) * 64 + o] = v.z * sc;
            wsp[(i * 8 + gb + 3) * 64 + o] = v.w * sc;
        }
        // base weights [i][o]: 512 tasks
#pragma unroll
        for (int r = 0; r < 4; r++) {
            int l = tid + r * 128;
            int o = l & 63;
            int i = l >> 6;
            wb[i * 64 + o] = base_w[(size_t)o * 256 + i0 + i];
        }
        // bases: 32 s x 8 i = 256 evals / 128 threads
#pragma unroll
        for (int r = 0; r < 2; r++) {
            int task = tid + r * 128;
            int s = task >> 3, i = task & 7;
            float bb8[8];
            bspline8(feat[s * 256 + i0 + i], bb8);
            float4* dst = reinterpret_cast<float4*>(&bas[(s * KIC + i) * 8]);
            dst[0] = make_float4(bb8[0], bb8[1], bb8[2], bb8[3]);
            dst[1] = make_float4(bb8[4], bb8[5], bb8[6], bb8[7]);
        }
        __syncthreads();

        for (int i = 0; i < KIC; i++) {
            float4 wbv = *reinterpret_cast<const float4*>(&wb[i * 64 + og * 4]);
            float wvp[32];
#pragma unroll
            for (int g = 0; g < 8; g++)
                *reinterpret_cast<float4*>(&wvp[g * 4]) =
                    *reinterpret_cast<const float4*>(&wsp[(i * 8 + g) * 64 + og * 4]);
#pragma unroll
            for (int ss = 0; ss < 4; ss++) {
                const int s = sg * 4 + ss;
                const float sv = sil[s * 256 + i0 + i];
                const float4* bp = reinterpret_cast<const float4*>(&bas[(s * KIC + i) * 8]);
                float4 bA = bp[0], bB = bp[1];
                float bv[8] = {bA.x, bA.y, bA.z, bA.w, bB.x, bB.y, bB.z, bB.w};
                acc[ss][0] = fmaf(sv, wbv.x, acc[ss][0]);
                acc[ss][1] = fmaf(sv, wbv.y, acc[ss][1]);
                acc[ss][2] = fmaf(sv, wbv.z, acc[ss][2]);
                acc[ss][3] = fmaf(sv, wbv.w, acc[ss][3]);
#pragma unroll
                for (int g = 0; g < 8; g++) {
                    acc[ss][0] = fmaf(bv[g], wvp[g * 4 + 0], acc[ss][0]);
                    acc[ss][1] = fmaf(bv[g], wvp[g * 4 + 1], acc[ss][1]);
                    acc[ss][2] = fmaf(bv[g], wvp[g * 4 + 2], acc[ss][2]);
                    acc[ss][3] = fmaf(bv[g], wvp[g * 4 + 3], acc[ss][3]);
                }
            }
        }
    }

#pragma unroll
    for (int ss = 0; ss < 4; ss++) {
        const int b = b0 + sg * 4 + ss;
        *reinterpret_cast<float4*>(&out[(size_t)b * 64 + og * 4]) =
            make_float4(acc[ss][0], acc[ss][1], acc[ss][2], acc[ss][3]);
    }
}

// ---------------------------------------------------------------------------
// Launch
// ---------------------------------------------------------------------------
extern "C" void kernel_launch(void* const* d_in, const int* in_sizes, int n_in,
                              void* d_out, int out_size)
{
    const float* x    = (const float*)d_in[0];
    const float* w    = (const float*)d_in[1];
    const float* bias = (const float*)d_in[2];
    const float* fc1w = (const float*)d_in[3];
    const float* fc1b = (const float*)d_in[4];
    const float* fc2w = (const float*)d_in[5];
    const float* fc2b = (const float*)d_in[6];
    const float* kbw  = (const float*)d_in[7];
    const float* ksw  = (const float*)d_in[8];
    const float* kss  = (const float*)d_in[9];
    float* out = (float*)d_out;

    cudaFuncSetAttribute(gemm_kernel, cudaFuncAttributeMaxDynamicSharedMemorySize, GEMM_SMEM);
    cudaFuncSetAttribute(kan_kernel,  cudaFuncAttributeMaxDynamicSharedMemorySize, KAN_SMEM_BYTES);

    prep_x_kernel<<<BATCH, 256>>>(x);
    prep_w_kernel<<<NDIM, 256>>>(w);
    attn_kernel<<<BATCH / 4, 256>>>(fc1w, fc1b, fc2w, fc2b);
    gemm_kernel<<<dim3(NDIM / NT, MROWS / MT), GTHREADS, GEMM_SMEM>>>(bias);
    kan_kernel<<<BATCH / KBT, 128, KAN_SMEM_BYTES>>>(kbw, ksw, kss, out);
}

// round 12
// speedup vs baseline: 3.3379x; 1.1317x over previous
#include <cuda_runtime.h>
#include <cuda_bf16.h>
#include <math.h>
#include <stdint.h>

#define BATCH 8192
#define CIN   256
#define NK    4
#define COUT  64
#define KD    2304            // conv im2col K = 9 ij * 256 c
#define MROWS (BATCH * 4)     // m = b*4 + p
#define NDIM  256             // n = o*4 + nk

// conv GEMM tiling
#define MT 64
#define NT 64
#define KC 64
#define NCHUNK (KD / KC)      // 36
#define GTHREADS 128

// KAN GEMM: K2 = 256 i * 16 (8 bases, silu, 7 pad)
#define K2    4096
#define NCH2  (K2 / 64)       // 64 chunks

// ---------------------------------------------------------------------------
// Static device scratch
// ---------------------------------------------------------------------------
__device__ __nv_bfloat16 g_Xth[(size_t)BATCH * 16 * 256];   // [b][q][c] hi
__device__ __nv_bfloat16 g_Xtl[(size_t)BATCH * 16 * 256];   // [b][q][c] lo
__device__ __nv_bfloat16 g_W2h[(size_t)NDIM * KD];
__device__ __nv_bfloat16 g_W2l[(size_t)NDIM * KD];
__device__ __nv_bfloat16 g_W2sh[(size_t)COUT * K2];         // kan weights hi
__device__ __nv_bfloat16 g_W2sl[(size_t)COUT * K2];         // kan weights lo
__device__ float g_feat[(size_t)BATCH * 256];
__device__ float g_attn[(size_t)BATCH * NK];

// ---------------------------------------------------------------------------
// PTX helpers
// ---------------------------------------------------------------------------
__device__ __forceinline__ unsigned smem_u32(const void* p) {
    unsigned a;
    asm("{ .reg .u64 t; cvta.to.shared.u64 t, %1; cvt.u32.u64 %0, t; }" : "=r"(a) : "l"(p));
    return a;
}
__device__ __forceinline__ void cp_async16(unsigned saddr, const void* g) {
    asm volatile("cp.async.cg.shared.global [%0], [%1], 16;" :: "r"(saddr), "l"(g));
}
#define CP_COMMIT() asm volatile("cp.async.commit_group;" ::: "memory")
#define CP_WAIT1()  asm volatile("cp.async.wait_group 1;" ::: "memory")

#define LDSM_X4(r0, r1, r2, r3, addr) \
    asm volatile("ldmatrix.sync.aligned.m8n8.x4.shared.b16 {%0,%1,%2,%3}, [%4];" \
                 : "=r"(r0), "=r"(r1), "=r"(r2), "=r"(r3) : "r"(addr))

#define MMA16816(c, a, b0, b1) \
    asm volatile("mma.sync.aligned.m16n8k16.row.col.f32.bf16.bf16.f32 " \
                 "{%0,%1,%2,%3}, {%4,%5,%6,%7}, {%8,%9}, {%0,%1,%2,%3};" \
                 : "+f"((c)[0]), "+f"((c)[1]), "+f"((c)[2]), "+f"((c)[3]) \
                 : "r"((a)[0]), "r"((a)[1]), "r"((a)[2]), "r"((a)[3]), \
                   "r"(b0), "r"(b1))

#define SWZ(o) ((o) ^ (((o) >> 3) & 0x70))

__device__ __forceinline__ unsigned pack_bf16(__nv_bfloat16 a, __nv_bfloat16 b) {
    __nv_bfloat162 t; t.x = a; t.y = b;
    return *reinterpret_cast<unsigned*>(&t);
}

// ---------------------------------------------------------------------------
// B-spline bases, grid matches the reference knots bit-exactly.
// ---------------------------------------------------------------------------
__device__ __forceinline__ void bspline8(float t, float* __restrict__ o8)
{
    float g[12];
#pragma unroll
    for (int j = 0; j < 12; j++)
        g[j] = __fadd_rn(__fmul_rn((float)(j - 3), 0.4f), -1.0f);
    float b[11];
#pragma unroll
    for (int j = 0; j < 11; j++)
        b[j] = (t >= g[j] && t < g[j + 1]) ? 1.0f : 0.0f;
#pragma unroll
    for (int k = 1; k <= 3; k++) {
#pragma unroll
        for (int j = 0; j < 10; j++) {
            if (j < 11 - k) {
                float left  = (t - g[j])         * (1.0f / (g[j + k] - g[j]));
                float right = (g[j + k + 1] - t) * (1.0f / (g[j + k + 1] - g[j + 1]));
                b[j] = left * b[j] + right * b[j + 1];
            }
        }
    }
#pragma unroll
    for (int j = 0; j < 8; j++) o8[j] = b[j];
}

// ---------------------------------------------------------------------------
// Prep 1: x -> xT[b][q][c] hi/lo bf16, fused GAP + FULL attention (fc1/fc2/softmax).
// One block per sample.
// ---------------------------------------------------------------------------
__global__ __launch_bounds__(256) void prep_x_kernel(
    const float* __restrict__ x,
    const float* __restrict__ fc1w, const float* __restrict__ fc1b,
    const float* __restrict__ fc2w, const float* __restrict__ fc2b)
{
    __shared__ __align__(16) __nv_bfloat16 sh[16 * 256];
    __shared__ __align__(16) __nv_bfloat16 sl[16 * 256];
    __shared__ __align__(16) float pooled[256];
    __shared__ float hpart[4][64];
    __shared__ float hid[64];
    __shared__ float logit[4];

    const int b = blockIdx.x, c = threadIdx.x;

    const float4* src = reinterpret_cast<const float4*>(x + ((size_t)b * CIN + c) * 16);
    float4 v[4];
#pragma unroll
    for (int i = 0; i < 4; i++) v[i] = src[i];
    const float* f = reinterpret_cast<const float*>(v);

    float sum = 0.f;
#pragma unroll
    for (int e = 0; e < 16; e++) {
        float fv = f[e];
        sum += fv;
        __nv_bfloat16 h = __float2bfloat16(fv);
        sh[e * 256 + c] = h;
        sl[e * 256 + c] = __float2bfloat16(fv - __bfloat162float(h));
    }
    pooled[c] = sum * (1.f / 16.f);
    __syncthreads();

    // flush xT
    const uint4* s4h = reinterpret_cast<const uint4*>(sh);
    const uint4* s4l = reinterpret_cast<const uint4*>(sl);
    uint4* dh = reinterpret_cast<uint4*>(g_Xth + (size_t)b * 16 * 256);
    uint4* dl = reinterpret_cast<uint4*>(g_Xtl + (size_t)b * 16 * 256);
    dh[c]       = s4h[c];
    dh[c + 256] = s4h[c + 256];
    dl[c]       = s4l[c];
    dl[c + 256] = s4l[c + 256];

    // ---- fused attention ----
    {
        const int h = c >> 2, part = c & 3;
        const float4* wr = reinterpret_cast<const float4*>(fc1w + (size_t)h * 256 + part * 64);
        const float4* pr = reinterpret_cast<const float4*>(pooled + part * 64);
        float s2 = 0.f;
#pragma unroll
        for (int q = 0; q < 16; q++) {
            float4 a = wr[q]; float4 bb = pr[q];
            s2 = fmaf(a.x, bb.x, s2); s2 = fmaf(a.y, bb.y, s2);
            s2 = fmaf(a.z, bb.z, s2); s2 = fmaf(a.w, bb.w, s2);
        }
        hpart[part][h] = s2;
    }
    __syncthreads();
    if (c < 64)
        hid[c] = fmaxf(hpart[0][c] + hpart[1][c] + hpart[2][c] + hpart[3][c] + fc1b[c], 0.f);
    __syncthreads();
    if (c < 4) {
        float sm = 0.f;
#pragma unroll
        for (int k2 = 0; k2 < 64; k2++) sm = fmaf(hid[k2], fc2w[c * 64 + k2], sm);
        logit[c] = (sm + fc2b[c]) * (1.0f / 34.0f);
    }
    __syncthreads();
    if (c == 0) {
        float l0 = logit[0], l1 = logit[1], l2 = logit[2], l3 = logit[3];
        float m  = fmaxf(fmaxf(l0, l1), fmaxf(l2, l3));
        float e0 = expf(l0 - m), e1 = expf(l1 - m), e2 = expf(l2 - m), e3 = expf(l3 - m);
        float inv = 1.f / (e0 + e1 + e2 + e3);
        g_attn[(size_t)b * 4 + 0] = e0 * inv;
        g_attn[(size_t)b * 4 + 1] = e1 * inv;
        g_attn[(size_t)b * 4 + 2] = e2 * inv;
        g_attn[(size_t)b * 4 + 3] = e3 * inv;
    }
}

// ---------------------------------------------------------------------------
// Prep 2: conv weights -> W2[n][k], n = o*4 + nk, k = ij*256 + c, hi/lo bf16.
// ---------------------------------------------------------------------------
__global__ __launch_bounds__(256) void prep_w_kernel(const float* __restrict__ w)
{
    const int n = blockIdx.x, c = threadIdx.x;
    const int o = n >> 2, nk = n & 3;
    const float* wr = w + ((size_t)(nk * COUT + o) * CIN + c) * 9;
#pragma unroll
    for (int ij = 0; ij < 9; ij++) {
        float val = wr[ij];
        __nv_bfloat16 h = __float2bfloat16(val);
        __nv_bfloat16 l = __float2bfloat16(val - __bfloat162float(h));
        g_W2h[(size_t)n * KD + ij * 256 + c] = h;
        g_W2l[(size_t)n * KD + ij * 256 + c] = l;
    }
}

// ---------------------------------------------------------------------------
// Prep 3: KAN weights -> W2s[o][k], k = i*16 + g; g 0..7 = spline_w*scaler,
//         g=8 = base_w, g 9..15 = 0. hi/lo bf16.
// ---------------------------------------------------------------------------
__global__ __launch_bounds__(256) void prep_w2_kernel(
    const float* __restrict__ base_w,
    const float* __restrict__ spline_w,
    const float* __restrict__ scaler)
{
    const int o = blockIdx.x, i = threadIdx.x;
    const float sc = scaler[(size_t)o * 256 + i];
    float vals[16];
#pragma unroll
    for (int g = 0; g < 8; g++)
        vals[g] = spline_w[((size_t)o * 256 + i) * 8 + g] * sc;
    vals[8] = base_w[(size_t)o * 256 + i];
#pragma unroll
    for (int g = 9; g < 16; g++) vals[g] = 0.f;

    unsigned hw[8], lw[8];
#pragma unroll
    for (int j = 0; j < 8; j++) {
        __nv_bfloat16 h0 = __float2bfloat16(vals[2 * j]);
        __nv_bfloat16 h1 = __float2bfloat16(vals[2 * j + 1]);
        __nv_bfloat16 l0 = __float2bfloat16(vals[2 * j] - __bfloat162float(h0));
        __nv_bfloat16 l1 = __float2bfloat16(vals[2 * j + 1] - __bfloat162float(h1));
        hw[j] = pack_bf16(h0, h1);
        lw[j] = pack_bf16(l0, l1);
    }
    uint4* dh = reinterpret_cast<uint4*>(g_W2sh + (size_t)o * K2 + i * 16);
    uint4* dl = reinterpret_cast<uint4*>(g_W2sl + (size_t)o * K2 + i * 16);
    dh[0] = make_uint4(hw[0], hw[1], hw[2], hw[3]);
    dh[1] = make_uint4(hw[4], hw[5], hw[6], hw[7]);
    dl[0] = make_uint4(lw[0], lw[1], lw[2], lw[3]);
    dl[1] = make_uint4(lw[4], lw[5], lw[6], lw[7]);
}

// ---------------------------------------------------------------------------
// Conv GEMM (unchanged from R11): CTA 64x64, 128 thr, 2-stage, 3 CTAs/SM.
// ---------------------------------------------------------------------------
#define ST_AH 0
#define ST_AL 8192
#define ST_BH 16384
#define ST_BL 24576
#define ST_SZ 32768
#define GEMM_SMEM (2 * ST_SZ)   // 65536

__global__ __launch_bounds__(GTHREADS, 3) void gemm_kernel(const float* __restrict__ bias)
{
    extern __shared__ __align__(1024) char smem[];
    __shared__ float bias_s[256];

    const unsigned sb = smem_u32(smem);
    const int tid = threadIdx.x;
    const int wid = tid >> 5, lane = tid & 31;
    const int wm = wid >> 1, wn = wid & 1;
    const int n0 = blockIdx.x * NT;
    const int m0 = blockIdx.y * MT;

    bias_s[tid] = bias[tid];
    bias_s[tid + 128] = bias[tid + 128];

    const char* Xh = (const char*)g_Xth;
    const char* Xl = (const char*)g_Xtl;
    const char* Wh = (const char*)g_W2h;
    const char* Wl = (const char*)g_W2l;

    auto load_chunk = [&](int ch, int stg) {
        const unsigned st = sb + stg * ST_SZ;
        const int ij = ch >> 2;
        const int cb = (ch & 3) * 64;
        const int di = ij / 3, dj = ij - di * 3;
        const size_t kb = (size_t)ch * 128;
#pragma unroll
        for (int i = 0; i < 4; i++) {
            int s = tid + i * GTHREADS;
            int row = s >> 3, seg = s & 7;
            unsigned so = SWZ(row * 128 + seg * 16);
            const int m = m0 + row;
            const int b = m >> 2, p = m & 3;
            const int q = ((p >> 1) + di) * 4 + (p & 1) + dj;
            size_t ga = ((size_t)b * 16 + q) * 512 + cb * 2 + seg * 16;
            cp_async16(st + ST_AH + so, Xh + ga);
            cp_async16(st + ST_AL + so, Xl + ga);
        }
#pragma unroll
        for (int i = 0; i < 4; i++) {
            int s = tid + i * GTHREADS;
            int row = s >> 3, seg = s & 7;
            unsigned so = SWZ(row * 128 + seg * 16);
            size_t gb = (size_t)(n0 + row) * (KD * 2) + kb + seg * 16;
            cp_async16(st + ST_BH + so, Wh + gb);
            cp_async16(st + ST_BL + so, Wl + gb);
        }
    };

    float cAcc[2][4][4];
#pragma unroll
    for (int m = 0; m < 2; m++)
#pragma unroll
        for (int n = 0; n < 4; n++)
#pragma unroll
            for (int r = 0; r < 4; r++) cAcc[m][n][r] = 0.f;

    load_chunk(0, 0); CP_COMMIT();
    load_chunk(1, 1); CP_COMMIT();

    const int arow = lane & 15;
    const int aseg = (lane >> 4) << 4;

    for (int ch = 0; ch < NCHUNK; ch++) {
        const int stg = ch & 1;
        const unsigned st = sb + stg * ST_SZ;
        CP_WAIT1();
        __syncthreads();

#pragma unroll
        for (int ks = 0; ks < 4; ks++) {
            const int kb2 = ks * 32 + aseg;
            unsigned ah[2][4], al[2][4], bh[2][4], bl[2][4];
#pragma unroll
            for (int mt = 0; mt < 2; mt++) {
                int r = wm * 32 + mt * 16 + arow;
                unsigned so = SWZ(r * 128 + kb2);
                LDSM_X4(ah[mt][0], ah[mt][1], ah[mt][2], ah[mt][3], st + ST_AH + so);
                LDSM_X4(al[mt][0], al[mt][1], al[mt][2], al[mt][3], st + ST_AL + so);
            }
#pragma unroll
            for (int nt2 = 0; nt2 < 2; nt2++) {
                int r = wn * 32 + nt2 * 16 + arow;
                unsigned so = SWZ(r * 128 + kb2);
                LDSM_X4(bh[nt2][0], bh[nt2][1], bh[nt2][2], bh[nt2][3], st + ST_BH + so);
                LDSM_X4(bl[nt2][0], bl[nt2][1], bl[nt2][2], bl[nt2][3], st + ST_BL + so);
            }
#pragma unroll
            for (int mt = 0; mt < 2; mt++)
#pragma unroll
                for (int nt2 = 0; nt2 < 2; nt2++)
#pragma unroll
                    for (int b3 = 0; b3 < 2; b3++)
                        MMA16816(cAcc[mt][nt2 * 2 + b3], ah[mt], bh[nt2][b3], bh[nt2][b3 + 2]);
#pragma unroll
            for (int mt = 0; mt < 2; mt++)
#pragma unroll
                for (int nt2 = 0; nt2 < 2; nt2++)
#pragma unroll
                    for (int b3 = 0; b3 < 2; b3++)
                        MMA16816(cAcc[mt][nt2 * 2 + b3], al[mt], bh[nt2][b3], bh[nt2][b3 + 2]);
#pragma unroll
            for (int mt = 0; mt < 2; mt++)
#pragma unroll
                for (int nt2 = 0; nt2 < 2; nt2++)
#pragma unroll
                    for (int b3 = 0; b3 < 2; b3++)
                        MMA16816(cAcc[mt][nt2 * 2 + b3], ah[mt], bl[nt2][b3], bl[nt2][b3 + 2]);
        }

        __syncthreads();
        if (ch + 2 < NCHUNK) load_chunk(ch + 2, stg);
        CP_COMMIT();
    }

    // epilogue: combine nk via lane-pair shfl, add bias, write g_feat
    const int j = lane & 3;
    const int rbase = wm * 32 + (lane >> 2);
#pragma unroll
    for (int mt = 0; mt < 2; mt++) {
#pragma unroll
        for (int h = 0; h < 2; h++) {
            const int m = m0 + rbase + mt * 16 + h * 8;
            const int b = m >> 2, p = m & 3;
            const float4 av = *reinterpret_cast<const float4*>(g_attn + (size_t)b * 4);
            const float a[4] = {av.x, av.y, av.z, av.w};
            const int nkb = (j & 1) * 2;
#pragma unroll
            for (int nt2 = 0; nt2 < 2; nt2++)
#pragma unroll
                for (int b3 = 0; b3 < 2; b3++) {
                    const float* c = cAcc[mt][nt2 * 2 + b3];
                    float partial = a[nkb] * c[h * 2 + 0] + a[nkb + 1] * c[h * 2 + 1];
                    partial += __shfl_xor_sync(0xffffffffu, partial, 1);
                    if ((j & 1) == 0) {
                        const int o = (n0 + wn * 32 + nt2 * 16 + b3 * 8) / 4 + (j >> 1);
                        const float bc = a[0] * bias_s[o] + a[1] * bias_s[64 + o]
                                       + a[2] * bias_s[128 + o] + a[3] * bias_s[192 + o];
                        g_feat[(size_t)b * 256 + o * 4 + p] = partial + bc;
                    }
                }
        }
    }
}

// ---------------------------------------------------------------------------
// KAN as HMMA GEMM: out[32768 x 64... actually 8192 x 64] = A · W2s^T.
// Block = 32 samples (M=32), N=64, K=4096 in 64 chunks of 64.
// A produced on the fly: per (s, i) -> 8 bases + silu + 7 zeros, bf16 hi/lo.
// 128 threads, 4 warps (2m x 2n), warp tile 16x32, 2-stage. 2 CTAs/SM.
// ---------------------------------------------------------------------------
#define K_AH 0
#define K_AL 4096
#define K_BH 8192
#define K_BL 16384
#define K_STSZ 24576
#define K_FEAT (2 * K_STSZ)                 // 49152
#define KAN2_SMEM (K_FEAT + 32 * 256 * 4)   // 81920

__global__ __launch_bounds__(128, 2) void kan2_kernel(float* __restrict__ out)
{
    extern __shared__ __align__(1024) char smem[];
    const unsigned sb = smem_u32(smem);
    float* feat = reinterpret_cast<float*>(smem + K_FEAT);

    const int tid = threadIdx.x;
    const int wid = tid >> 5, lane = tid & 31;
    const int wm = wid >> 1, wn = wid & 1;
    const int b0 = blockIdx.x * 32;

    // load feat [32][256]
    {
        const float4* src = reinterpret_cast<const float4*>(g_feat + (size_t)b0 * 256);
#pragma unroll
        for (int r = 0; r < 16; r++) {
            int idx4 = tid + r * 128;
            *reinterpret_cast<float4*>(&feat[idx4 * 4]) = src[idx4];
        }
    }
    __syncthreads();

    const char* Bh = (const char*)g_W2sh;
    const char* Bl = (const char*)g_W2sl;

    // produce A chunk: 4 i x 32 s, 1 (s,i) per thread
    auto produce_A = [&](int ch, int stg) {
        const unsigned st = sb + stg * K_STSZ;
        const int s = tid & 31, il = tid >> 5;
        const int i = ch * 4 + il;
        const float t = feat[s * 256 + i];
        float vals[16];
        bspline8(t, vals);
        vals[8] = t / (1.f + expf(-t));
#pragma unroll
        for (int g = 9; g < 16; g++) vals[g] = 0.f;
        unsigned hw[8], lw[8];
#pragma unroll
        for (int j2 = 0; j2 < 8; j2++) {
            __nv_bfloat16 h0 = __float2bfloat16(vals[2 * j2]);
            __nv_bfloat16 h1 = __float2bfloat16(vals[2 * j2 + 1]);
            __nv_bfloat16 l0 = __float2bfloat16(vals[2 * j2] - __bfloat162float(h0));
            __nv_bfloat16 l1 = __float2bfloat16(vals[2 * j2 + 1] - __bfloat162float(h1));
            hw[j2] = pack_bf16(h0, h1);
            lw[j2] = pack_bf16(l0, l1);
        }
        const unsigned base = s * 128 + il * 32;
        *reinterpret_cast<uint4*>(smem + stg * K_STSZ + K_AH + SWZ(base)) =
            make_uint4(hw[0], hw[1], hw[2], hw[3]);
        *reinterpret_cast<uint4*>(smem + stg * K_STSZ + K_AH + SWZ(base + 16)) =
            make_uint4(hw[4], hw[5], hw[6], hw[7]);
        *reinterpret_cast<uint4*>(smem + stg * K_STSZ + K_AL + SWZ(base)) =
            make_uint4(lw[0], lw[1], lw[2], lw[3]);
        *reinterpret_cast<uint4*>(smem + stg * K_STSZ + K_AL + SWZ(base + 16)) =
            make_uint4(lw[4], lw[5], lw[6], lw[7]);
    };

    // load B chunk: 64 rows x 8 segs, hi+lo
    auto load_B = [&](int ch, int stg) {
        const unsigned st = sb + stg * K_STSZ;
        const size_t kb = (size_t)ch * 128;
#pragma unroll
        for (int i = 0; i < 4; i++) {
            int s = tid + i * 128;
            int row = s >> 3, seg = s & 7;
            unsigned so = SWZ(row * 128 + seg * 16);
            size_t gb = (size_t)row * (K2 * 2) + kb + seg * 16;
            cp_async16(st + K_BH + so, Bh + gb);
            cp_async16(st + K_BL + so, Bl + gb);
        }
    };

    float cAcc[4][4];
#pragma unroll
    for (int n = 0; n < 4; n++)
#pragma unroll
        for (int r = 0; r < 4; r++) cAcc[n][r] = 0.f;

    produce_A(0, 0); load_B(0, 0); CP_COMMIT();
    produce_A(1, 1); load_B(1, 1); CP_COMMIT();

    const int arow = lane & 15;
    const int aseg = (lane >> 4) << 4;

    for (int ch = 0; ch < NCH2; ch++) {
        const int stg = ch & 1;
        const unsigned st = sb + stg * K_STSZ;
        CP_WAIT1();
        __syncthreads();

#pragma unroll
        for (int ks = 0; ks < 4; ks++) {
            const int kb2 = ks * 32 + aseg;
            unsigned ah[4], al[4], bh[2][4], bl[2][4];
            {
                int r = wm * 16 + arow;
                unsigned so = SWZ(r * 128 + kb2);
                LDSM_X4(ah[0], ah[1], ah[2], ah[3], st + K_AH + so);
                LDSM_X4(al[0], al[1], al[2], al[3], st + K_AL + so);
            }
#pragma unroll
            for (int nt2 = 0; nt2 < 2; nt2++) {
                int r = wn * 32 + nt2 * 16 + arow;
                unsigned so = SWZ(r * 128 + kb2);
                LDSM_X4(bh[nt2][0], bh[nt2][1], bh[nt2][2], bh[nt2][3], st + K_BH + so);
                LDSM_X4(bl[nt2][0], bl[nt2][1], bl[nt2][2], bl[nt2][3], st + K_BL + so);
            }
#pragma unroll
            for (int nt2 = 0; nt2 < 2; nt2++)
#pragma unroll
                for (int b3 = 0; b3 < 2; b3++)
                    MMA16816(cAcc[nt2 * 2 + b3], ah, bh[nt2][b3], bh[nt2][b3 + 2]);
#pragma unroll
            for (int nt2 = 0; nt2 < 2; nt2++)
#pragma unroll
                for (int b3 = 0; b3 < 2; b3++)
                    MMA16816(cAcc[nt2 * 2 + b3], al, bh[nt2][b3], bh[nt2][b3 + 2]);
#pragma unroll
            for (int nt2 = 0; nt2 < 2; nt2++)
#pragma unroll
                for (int b3 = 0; b3 < 2; b3++)
                    MMA16816(cAcc[nt2 * 2 + b3], ah, bl[nt2][b3], bl[nt2][b3 + 2]);
        }

        __syncthreads();
        if (ch + 2 < NCH2) { produce_A(ch + 2, stg); load_B(ch + 2, stg); }
        CP_COMMIT();
    }

    // epilogue: direct write, standard m16n8 accumulator layout
    const int row = wm * 16 + (lane >> 2);
    const int colb = wn * 32 + (lane & 3) * 2;
#pragma unroll
    for (int nt2 = 0; nt2 < 2; nt2++)
#pragma unroll
        for (int b3 = 0; b3 < 2; b3++) {
            const float* c = cAcc[nt2 * 2 + b3];
            const int col = colb + nt2 * 16 + b3 * 8;
            *reinterpret_cast<float2*>(&out[(size_t)(b0 + row) * 64 + col]) =
                make_float2(c[0], c[1]);
            *reinterpret_cast<float2*>(&out[(size_t)(b0 + row + 8) * 64 + col]) =
                make_float2(c[2], c[3]);
        }
}

// ---------------------------------------------------------------------------
// Launch
// ---------------------------------------------------------------------------
extern "C" void kernel_launch(void* const* d_in, const int* in_sizes, int n_in,
                              void* d_out, int out_size)
{
    const float* x    = (const float*)d_in[0];
    const float* w    = (const float*)d_in[1];
    const float* bias = (const float*)d_in[2];
    const float* fc1w = (const float*)d_in[3];
    const float* fc1b = (const float*)d_in[4];
    const float* fc2w = (const float*)d_in[5];
    const float* fc2b = (const float*)d_in[6];
    const float* kbw  = (const float*)d_in[7];
    const float* ksw  = (const float*)d_in[8];
    const float* kss  = (const float*)d_in[9];
    float* out = (float*)d_out;

    cudaFuncSetAttribute(gemm_kernel, cudaFuncAttributeMaxDynamicSharedMemorySize, GEMM_SMEM);
    cudaFuncSetAttribute(kan2_kernel, cudaFuncAttributeMaxDynamicSharedMemorySize, KAN2_SMEM);

    prep_x_kernel<<<BATCH, 256>>>(x, fc1w, fc1b, fc2w, fc2b);
    prep_w_kernel<<<NDIM, 256>>>(w);
    prep_w2_kernel<<<COUT, 256>>>(kbw, ksw, kss);
    gemm_kernel<<<dim3(NDIM / NT, MROWS / MT), GTHREADS, GEMM_SMEM>>>(bias);
    kan2_kernel<<<BATCH / 32, 128, KAN2_SMEM>>>(out);
}